// round 1
// baseline (speedup 1.0000x reference)
#include <cuda_runtime.h>

#define B_   2
#define T_   4096
#define D_   768
#define H_   12
#define HD_  64
#define SCALE_ 0.125f

#define QT 128     // q-tile rows
#define KT 64      // k-tile cols

// ---------------- scratch (static device allocations) ----------------
__device__ float g_q[(size_t)B_ * H_ * T_ * HD_];   // [B,H,T,hd]
__device__ float g_k[(size_t)B_ * H_ * T_ * HD_];
__device__ float g_v[(size_t)B_ * H_ * T_ * HD_];
__device__ float g_att[(size_t)B_ * T_ * D_];       // [B,T,D]

// ======================================================================
// Tiled fp32 GEMM: C[M,N] = A[M,K] @ B[K,N] + bias
// mode 0: A = x, outputs scattered into g_q/g_k/g_v ([B,H,T,hd] layout)
// mode 1: A = g_att (A arg ignored), C = d_out plain row-major
// ======================================================================
#define GBM 128
#define GBN 128
#define GBK 16

__global__ void __launch_bounds__(256) gemm_kernel(
    const float* __restrict__ A, const float* __restrict__ Bm,
    const float* __restrict__ bias, float* __restrict__ C,
    int M, int N, int K, int mode)
{
    __shared__ float As[GBK][GBM + 4];   // transposed A tile, +4 pad
    __shared__ float Bs[GBK][GBN];

    const float* Ap = (mode == 1) ? g_att : A;

    const int bm = blockIdx.y * GBM;
    const int bn = blockIdx.x * GBN;
    const int tid = threadIdx.x;
    const int tx = tid & 15;
    const int ty = tid >> 4;

    const int arow = tid >> 2;          // 0..63
    const int acol = (tid & 3) * 4;     // 0,4,8,12
    const int brow = tid >> 5;          // 0..7
    const int bcol = (tid & 31) * 4;    // 0..124

    float acc[8][8];
#pragma unroll
    for (int i = 0; i < 8; i++)
#pragma unroll
        for (int j = 0; j < 8; j++) acc[i][j] = 0.f;

    for (int k0 = 0; k0 < K; k0 += GBK) {
#pragma unroll
        for (int p = 0; p < 2; p++) {
            float4 a = *(const float4*)&Ap[(size_t)(bm + arow + p * 64) * K + k0 + acol];
            As[acol + 0][arow + p * 64] = a.x;
            As[acol + 1][arow + p * 64] = a.y;
            As[acol + 2][arow + p * 64] = a.z;
            As[acol + 3][arow + p * 64] = a.w;
        }
#pragma unroll
        for (int p = 0; p < 2; p++) {
            *(float4*)&Bs[brow + p * 8][bcol] =
                *(const float4*)&Bm[(size_t)(k0 + brow + p * 8) * N + bn + bcol];
        }
        __syncthreads();

#pragma unroll
        for (int kk = 0; kk < GBK; kk++) {
            float ra[8], rb[8];
            *(float4*)&ra[0] = *(const float4*)&As[kk][ty * 8];
            *(float4*)&ra[4] = *(const float4*)&As[kk][ty * 8 + 4];
            *(float4*)&rb[0] = *(const float4*)&Bs[kk][tx * 8];
            *(float4*)&rb[4] = *(const float4*)&Bs[kk][tx * 8 + 4];
#pragma unroll
            for (int i = 0; i < 8; i++)
#pragma unroll
                for (int j = 0; j < 8; j++)
                    acc[i][j] = fmaf(ra[i], rb[j], acc[i][j]);
        }
        __syncthreads();
    }

    // -------- epilogue --------
    const int m0 = bm + ty * 8;
    const int n0 = bn + tx * 8;
    float bv[8];
#pragma unroll
    for (int j = 0; j < 8; j++) bv[j] = bias[n0 + j];

    if (mode == 1) {
#pragma unroll
        for (int i = 0; i < 8; i++) {
            float o[8];
#pragma unroll
            for (int j = 0; j < 8; j++) o[j] = acc[i][j] + bv[j];
            size_t base = (size_t)(m0 + i) * N + n0;
            *(float4*)&C[base]     = *(float4*)&o[0];
            *(float4*)&C[base + 4] = *(float4*)&o[4];
        }
    } else {
        // scatter into q/k/v [B,H,T,hd]. n0 block never straddles sel/head
        // boundary: n0 multiple of 8, heads are 64 wide, sel 768 wide.
        const int sel = n0 / D_;
        const int rem = n0 % D_;
        const int h   = rem / HD_;
        const int d0  = rem % HD_;
        float* dst = (sel == 0) ? g_q : ((sel == 1) ? g_k : g_v);
#pragma unroll
        for (int i = 0; i < 8; i++) {
            const int m = m0 + i;
            const int b = m / T_;
            const int t = m % T_;
            float o[8];
#pragma unroll
            for (int j = 0; j < 8; j++) o[j] = acc[i][j] + bv[j];
            size_t base = ((size_t)(b * H_ + h) * T_ + t) * HD_ + d0;
            *(float4*)&dst[base]     = *(float4*)&o[0];
            *(float4*)&dst[base + 4] = *(float4*)&o[4];
        }
    }
}

// ======================================================================
// Causal flash attention, fp32, online softmax.
// Block = (b, h, q-tile of 128 rows). 256 threads: ty=tid/16 -> 8 rows
// each, tx=tid%16 -> 4 hd-cols / 4 k-cols each.
// smem: Q[128][64], K^T[64][68], V[64][64], P[128][68]  (=101376 B)
// ======================================================================
__global__ void __launch_bounds__(256, 2) attn_kernel()
{
    extern __shared__ float sm[];
    float* sQ  = sm;                          // 128*64
    float* sKT = sQ  + QT * HD_;              // 64*68  (transposed: [d][c])
    float* sV  = sKT + HD_ * 68;              // 64*64
    float* sP  = sV  + KT * HD_;              // 128*68

    const int qi = (int)gridDim.x - 1 - (int)blockIdx.x;  // big tiles first
    const int h  = blockIdx.y;
    const int b  = blockIdx.z;
    const int qbase = qi * QT;

    const float* qptr = g_q + ((size_t)(b * H_ + h) * T_ + qbase) * HD_;
    const float* kptr = g_k + ((size_t)(b * H_ + h) * T_) * HD_;
    const float* vptr = g_v + ((size_t)(b * H_ + h) * T_) * HD_;

    const int tid = threadIdx.x;
    const int tx = tid & 15;
    const int ty = tid >> 4;

    // load Q tile (coalesced)
    {
        const int r  = tid >> 4;
        const int c4 = (tid & 15) * 4;
#pragma unroll
        for (int p = 0; p < 8; p++)
            *(float4*)&sQ[(r + p * 16) * HD_ + c4] =
                *(const float4*)&qptr[(size_t)(r + p * 16) * HD_ + c4];
    }

    float m[8], l[8];
    float4 o[8];
#pragma unroll
    for (int i = 0; i < 8; i++) {
        m[i] = -1e30f; l[i] = 0.f;
        o[i] = make_float4(0.f, 0.f, 0.f, 0.f);
    }

    const int nkt = qbase / KT + 2;   // k-tiles with kb <= qbase+127

    for (int kt = 0; kt < nkt; kt++) {
        const int kb = kt * KT;
        __syncthreads();   // protect smem reuse (and Q stores on kt==0)

        // load K (transposed into sKT) and V
        {
            const int r  = tid >> 4;
            const int c4 = (tid & 15) * 4;
#pragma unroll
            for (int p = 0; p < 4; p++) {
                const int row = r + p * 16;   // 0..63
                float4 kv = *(const float4*)&kptr[(size_t)(kb + row) * HD_ + c4];
                sKT[(c4 + 0) * 68 + row] = kv.x;
                sKT[(c4 + 1) * 68 + row] = kv.y;
                sKT[(c4 + 2) * 68 + row] = kv.z;
                sKT[(c4 + 3) * 68 + row] = kv.w;
                *(float4*)&sV[row * HD_ + c4] =
                    *(const float4*)&vptr[(size_t)(kb + row) * HD_ + c4];
            }
        }
        __syncthreads();

        // S = Q @ K^T  (8 rows x 4 cols per thread)
        float s[8][4];
#pragma unroll
        for (int i = 0; i < 8; i++)
#pragma unroll
            for (int j = 0; j < 4; j++) s[i][j] = 0.f;

#pragma unroll
        for (int d4 = 0; d4 < HD_; d4 += 4) {
            float kjf[16];
#pragma unroll
            for (int dd = 0; dd < 4; dd++)
                *(float4*)&kjf[dd * 4] = *(const float4*)&sKT[(d4 + dd) * 68 + tx * 4];
#pragma unroll
            for (int i = 0; i < 8; i++) {
                float qvf[4];
                *(float4*)&qvf[0] = *(const float4*)&sQ[(ty * 8 + i) * HD_ + d4];
#pragma unroll
                for (int dd = 0; dd < 4; dd++)
#pragma unroll
                    for (int j = 0; j < 4; j++)
                        s[i][j] = fmaf(qvf[dd], kjf[dd * 4 + j], s[i][j]);
            }
        }

        // scale + causal mask
#pragma unroll
        for (int i = 0; i < 8; i++) {
            const int gq = qbase + ty * 8 + i;
#pragma unroll
            for (int j = 0; j < 4; j++) {
                const int gk = kb + tx * 4 + j;
                s[i][j] = (gk <= gq) ? s[i][j] * SCALE_ : -1e30f;
            }
        }

        // online softmax (row groups = 16 lanes sharing ty)
#pragma unroll
        for (int i = 0; i < 8; i++) {
            float mx = fmaxf(fmaxf(s[i][0], s[i][1]), fmaxf(s[i][2], s[i][3]));
#pragma unroll
            for (int off = 8; off >= 1; off >>= 1)
                mx = fmaxf(mx, __shfl_xor_sync(0xffffffffu, mx, off));
            const float mnew = fmaxf(m[i], mx);
            const float corr = __expf(m[i] - mnew);
            float sum = 0.f;
#pragma unroll
            for (int j = 0; j < 4; j++) {
                const float p = __expf(s[i][j] - mnew);
                s[i][j] = p;
                sum += p;
            }
#pragma unroll
            for (int off = 8; off >= 1; off >>= 1)
                sum += __shfl_xor_sync(0xffffffffu, sum, off);
            l[i] = l[i] * corr + sum;
            m[i] = mnew;
            o[i].x *= corr; o[i].y *= corr; o[i].z *= corr; o[i].w *= corr;
            *(float4*)&sP[(ty * 8 + i) * 68 + tx * 4] =
                make_float4(s[i][0], s[i][1], s[i][2], s[i][3]);
        }
        __syncthreads();

        // O += P @ V
#pragma unroll
        for (int c4 = 0; c4 < KT; c4 += 4) {
            float4 vr[4];
#pragma unroll
            for (int j = 0; j < 4; j++)
                vr[j] = *(const float4*)&sV[(c4 + j) * HD_ + tx * 4];
#pragma unroll
            for (int i = 0; i < 8; i++) {
                float pvf[4];
                *(float4*)&pvf[0] = *(const float4*)&sP[(ty * 8 + i) * 68 + c4];
#pragma unroll
                for (int j = 0; j < 4; j++) {
                    o[i].x = fmaf(pvf[j], vr[j].x, o[i].x);
                    o[i].y = fmaf(pvf[j], vr[j].y, o[i].y);
                    o[i].z = fmaf(pvf[j], vr[j].z, o[i].z);
                    o[i].w = fmaf(pvf[j], vr[j].w, o[i].w);
                }
            }
        }
    }

    // normalize + write to g_att [B,T,D]
#pragma unroll
    for (int i = 0; i < 8; i++) {
        const float inv = 1.f / l[i];
        const int t = qbase + ty * 8 + i;
        float4 res = make_float4(o[i].x * inv, o[i].y * inv, o[i].z * inv, o[i].w * inv);
        *(float4*)&g_att[((size_t)(b * T_ + t)) * D_ + h * HD_ + tx * 4] = res;
    }
}

// ======================================================================
extern "C" void kernel_launch(void* const* d_in, const int* in_sizes, int n_in,
                              void* d_out, int out_size)
{
    const float* x      = (const float*)d_in[0];
    const float* W_qkv  = (const float*)d_in[1];
    const float* b_qkv  = (const float*)d_in[2];
    const float* W_out  = (const float*)d_in[3];
    const float* b_out  = (const float*)d_in[4];
    float* out = (float*)d_out;

    // 1) QKV projection -> g_q/g_k/g_v
    {
        dim3 grid((3 * D_) / GBN, (B_ * T_) / GBM);
        gemm_kernel<<<grid, 256>>>(x, W_qkv, b_qkv, nullptr,
                                   B_ * T_, 3 * D_, D_, 0);
    }

    // 2) causal flash attention -> g_att
    {
        const size_t smem = (size_t)(QT * HD_ + HD_ * 68 + KT * HD_ + QT * 68) * sizeof(float);
        cudaFuncSetAttribute(attn_kernel,
                             cudaFuncAttributeMaxDynamicSharedMemorySize, (int)smem);
        dim3 grid(T_ / QT, H_, B_);
        attn_kernel<<<grid, 256, smem>>>();
    }

    // 3) output projection -> d_out
    {
        dim3 grid(D_ / GBN, (B_ * T_) / GBM);
        gemm_kernel<<<grid, 256>>>(nullptr, W_out, b_out, out,
                                   B_ * T_, D_, D_, 1);
    }
}

// round 3
// speedup vs baseline: 1.1441x; 1.1441x over previous
#include <cuda_runtime.h>
#include <cuda_bf16.h>
#include <cstdint>

#define B_   2
#define T_   4096
#define D_   768
#define H_   12
#define HD_  64
#define SCALE_ 0.125f

#define QT 128     // attention q-tile rows
#define KT 64      // attention k-tile cols

// ---------------- scratch (static device allocations) ----------------
__device__ float g_q[(size_t)B_ * H_ * T_ * HD_];   // [B,H,T,hd]
__device__ float g_k[(size_t)B_ * H_ * T_ * HD_];
__device__ float g_v[(size_t)B_ * H_ * T_ * HD_];
__device__ float g_att[(size_t)B_ * T_ * D_];       // [B,T,D]

// bf16 split buffers
__device__ __nv_bfloat16 g_xh[(size_t)B_ * T_ * D_];
__device__ __nv_bfloat16 g_xl[(size_t)B_ * T_ * D_];
__device__ __nv_bfloat16 g_ah[(size_t)B_ * T_ * D_];
__device__ __nv_bfloat16 g_al[(size_t)B_ * T_ * D_];
__device__ __nv_bfloat16 g_wqh[(size_t)3 * D_ * D_];   // W_qkv^T [N=2304][K=768]
__device__ __nv_bfloat16 g_wql[(size_t)3 * D_ * D_];
__device__ __nv_bfloat16 g_woh[(size_t)D_ * D_];       // W_out^T [768][768]
__device__ __nv_bfloat16 g_wol[(size_t)D_ * D_];

// ======================= helpers ========================
__device__ __forceinline__ uint32_t smem_u32(const void* p) {
    uint32_t a;
    asm("{ .reg .u64 t; cvta.to.shared.u64 t, %1; cvt.u32.u64 %0, t; }"
        : "=r"(a) : "l"(p));
    return a;
}

__device__ __forceinline__ void cp16(uint32_t s, const void* g) {
    asm volatile("cp.async.cg.shared.global [%0], [%1], 16;" :: "r"(s), "l"(g));
}
#define CP_COMMIT() asm volatile("cp.async.commit_group;" ::: "memory")
#define CP_WAIT1()  asm volatile("cp.async.wait_group 1;" ::: "memory")
#define CP_WAIT0()  asm volatile("cp.async.wait_group 0;" ::: "memory")

// bf16 HMMA m16n8k16, fp32 accumulate (arch-generic tensor path)
__device__ __forceinline__ void mma16816(float* c, const uint32_t* a, const uint32_t* b) {
    asm volatile(
        "mma.sync.aligned.m16n8k16.row.col.f32.bf16.bf16.f32 "
        "{%0,%1,%2,%3}, {%4,%5,%6,%7}, {%8,%9}, {%0,%1,%2,%3};"
        : "+f"(c[0]), "+f"(c[1]), "+f"(c[2]), "+f"(c[3])
        : "r"(a[0]), "r"(a[1]), "r"(a[2]), "r"(a[3]), "r"(b[0]), "r"(b[1]));
}

// ======================================================================
// fp32 -> bf16 (hi, lo) split, elementwise
// ======================================================================
__global__ void conv_split(const float* __restrict__ in,
                           __nv_bfloat16* __restrict__ oh,
                           __nv_bfloat16* __restrict__ ol, int n)
{
    int i = blockIdx.x * blockDim.x + threadIdx.x;
    if (i >= n) return;
    float v = in[i];
    __nv_bfloat16 h = __float2bfloat16_rn(v);
    float r = v - __bfloat162float(h);
    oh[i] = h;
    ol[i] = __float2bfloat16_rn(r);
}

// fp32 [K][N] -> bf16 split, transposed to [N][K]
__global__ void conv_split_tr(const float* __restrict__ in,
                              __nv_bfloat16* __restrict__ oh,
                              __nv_bfloat16* __restrict__ ol, int K, int N)
{
    int i = blockIdx.x * blockDim.x + threadIdx.x;
    if (i >= K * N) return;
    int k = i / N, n = i % N;
    float v = in[i];
    __nv_bfloat16 h = __float2bfloat16_rn(v);
    float r = v - __bfloat162float(h);
    oh[(size_t)n * K + k] = h;
    ol[(size_t)n * K + k] = __float2bfloat16_rn(r);
}

// ======================================================================
// HMMA GEMM, bf16 split (hi*hi + hi*lo + lo*hi), C = A @ B_stored^T + bias
// A: [M][K] bf16 (hi,lo); B: [N][K] bf16 (hi,lo). Block tile 128x128,
// K-chunk 64, cp.async double buffer. 8 warps in 4(M)x2(N), warp tile 32x64.
// mode 0: scatter into g_q/g_k/g_v; mode 1: plain row-major Cout.
// ======================================================================
#define LDK 72                      // padded row length (bf16) -> conflict-free frags
#define TILE_B (128 * LDK * 2)      // 18432 bytes per tile
#define TOFF(buf, t) (((buf) * 4 + (t)) * TILE_B)
#define SMEM_GT (2 * 4 * TILE_B)    // 147456

__global__ void __launch_bounds__(256, 1) gemm_tc_mma(
    const __nv_bfloat16* __restrict__ Ah, const __nv_bfloat16* __restrict__ Al,
    const __nv_bfloat16* __restrict__ Bh, const __nv_bfloat16* __restrict__ Bl,
    const float* __restrict__ bias, float* __restrict__ Cout,
    int M, int N, int K, int mode)
{
    extern __shared__ char smc[];
    const uint32_t sbase = smem_u32(smc);
    const int tid  = threadIdx.x;
    const int lane = tid & 31;
    const int wid  = tid >> 5;
    const int wm   = wid & 3;        // warp M index (0..3)
    const int wn   = wid >> 2;       // warp N index (0..1)
    const int bm = blockIdx.y * 128;
    const int bn = blockIdx.x * 128;

    const char* gA[2] = { (const char*)(Ah + (size_t)bm * K),
                          (const char*)(Al + (size_t)bm * K) };
    const char* gB[2] = { (const char*)(Bh + (size_t)bn * K),
                          (const char*)(Bl + (size_t)bn * K) };

    const int nk = K / 64;

    // cp.async loader: chunk k0 -> buffer buf (4 tiles x 1024 x 16B)
    auto issue_chunk = [&](int k0, int buf) {
#pragma unroll
        for (int t = 0; t < 4; t++) {
            const char* src = (t < 2) ? gA[t] : gB[t - 2];
#pragma unroll
            for (int j = 0; j < 4; j++) {
                const int idx = tid * 4 + j;       // 0..1023
                const int row = idx >> 3;          // 0..127
                const int c16 = idx & 7;           // 0..7 (16B units)
                cp16(sbase + TOFF(buf, t) + row * (LDK * 2) + c16 * 16,
                     src + (size_t)row * (K * 2) + k0 * 2 + c16 * 16);
            }
        }
    };

    issue_chunk(0, 0); CP_COMMIT();
    if (nk > 1) { issue_chunk(64, 1); }
    CP_COMMIT();

    float acc[2][8][4];
#pragma unroll
    for (int i = 0; i < 2; i++)
#pragma unroll
        for (int j = 0; j < 8; j++)
#pragma unroll
            for (int q = 0; q < 4; q++) acc[i][j][q] = 0.f;

    const int lr = lane >> 2;          // 0..7
    const int lc = (lane & 3) * 2;     // 0,2,4,6

    for (int it = 0; it < nk; ++it) {
        const int buf = it & 1;
        CP_WAIT1();
        __syncthreads();

        const char* sA[2] = { smc + TOFF(buf, 0), smc + TOFF(buf, 1) };
        const char* sB[2] = { smc + TOFF(buf, 2), smc + TOFF(buf, 3) };

#pragma unroll
        for (int kk = 0; kk < 4; kk++) {
            const int kb = kk * 32 + lc * 2;     // byte offset of k=lc within chunk
            // A fragments (hi, lo): 2 m-tiles each
            uint32_t af[2][2][4];
#pragma unroll
            for (int v = 0; v < 2; v++)
#pragma unroll
                for (int i = 0; i < 2; i++) {
                    const int r0 = (wm * 32 + i * 16 + lr) * (LDK * 2);
                    af[v][i][0] = *(const uint32_t*)(sA[v] + r0 + kb);
                    af[v][i][1] = *(const uint32_t*)(sA[v] + r0 + 8 * (LDK * 2) + kb);
                    af[v][i][2] = *(const uint32_t*)(sA[v] + r0 + kb + 16);
                    af[v][i][3] = *(const uint32_t*)(sA[v] + r0 + 8 * (LDK * 2) + kb + 16);
                }
            // B fragments (hi, lo): 8 n-tiles each
            uint32_t bf[2][8][2];
#pragma unroll
            for (int v = 0; v < 2; v++)
#pragma unroll
                for (int j = 0; j < 8; j++) {
                    const int n0 = (wn * 64 + j * 8 + lr) * (LDK * 2);
                    bf[v][j][0] = *(const uint32_t*)(sB[v] + n0 + kb);
                    bf[v][j][1] = *(const uint32_t*)(sB[v] + n0 + kb + 16);
                }
#pragma unroll
            for (int i = 0; i < 2; i++)
#pragma unroll
                for (int j = 0; j < 8; j++) {
                    mma16816(acc[i][j], af[0][i], bf[0][j]);   // hi*hi
                    mma16816(acc[i][j], af[0][i], bf[1][j]);   // hi*lo
                    mma16816(acc[i][j], af[1][i], bf[0][j]);   // lo*hi
                }
        }
        __syncthreads();
        if (it + 2 < nk) { issue_chunk((it + 2) * 64, buf); }
        CP_COMMIT();
    }

    // -------- epilogue --------
#pragma unroll
    for (int i = 0; i < 2; i++) {
        const int row0 = bm + wm * 32 + i * 16 + lr;
#pragma unroll
        for (int j = 0; j < 8; j++) {
            const int col = bn + wn * 64 + j * 8 + lc;
            const float b0 = bias[col], b1 = bias[col + 1];
            float2 lo = make_float2(acc[i][j][0] + b0, acc[i][j][1] + b1);
            float2 hi = make_float2(acc[i][j][2] + b0, acc[i][j][3] + b1);
            if (mode == 1) {
                *(float2*)&Cout[(size_t)row0 * N + col]       = lo;
                *(float2*)&Cout[(size_t)(row0 + 8) * N + col] = hi;
            } else {
                const int sel = col / D_;
                const int rem = col % D_;
                const int h   = rem / HD_;
                const int d0  = rem % HD_;
                float* dst = (sel == 0) ? g_q : ((sel == 1) ? g_k : g_v);
                const int bb0 = row0 >> 12, t0 = row0 & (T_ - 1);
                const int bb1 = (row0 + 8) >> 12, t1 = (row0 + 8) & (T_ - 1);
                *(float2*)&dst[((size_t)(bb0 * H_ + h) * T_ + t0) * HD_ + d0] = lo;
                *(float2*)&dst[((size_t)(bb1 * H_ + h) * T_ + t1) * HD_ + d0] = hi;
            }
        }
    }
    CP_WAIT0();
}

// ======================================================================
// Causal flash attention, fp32, online softmax (unchanged — round 1 passing).
// ======================================================================
__global__ void __launch_bounds__(256, 2) attn_kernel()
{
    extern __shared__ float sm[];
    float* sQ  = sm;                          // 128*64
    float* sKT = sQ  + QT * HD_;              // 64*68
    float* sV  = sKT + HD_ * 68;              // 64*64
    float* sP  = sV  + KT * HD_;              // 128*68

    const int qi = (int)gridDim.x - 1 - (int)blockIdx.x;
    const int h  = blockIdx.y;
    const int b  = blockIdx.z;
    const int qbase = qi * QT;

    const float* qptr = g_q + ((size_t)(b * H_ + h) * T_ + qbase) * HD_;
    const float* kptr = g_k + ((size_t)(b * H_ + h) * T_) * HD_;
    const float* vptr = g_v + ((size_t)(b * H_ + h) * T_) * HD_;

    const int tid = threadIdx.x;
    const int tx = tid & 15;
    const int ty = tid >> 4;

    {
        const int r  = tid >> 4;
        const int c4 = (tid & 15) * 4;
#pragma unroll
        for (int p = 0; p < 8; p++)
            *(float4*)&sQ[(r + p * 16) * HD_ + c4] =
                *(const float4*)&qptr[(size_t)(r + p * 16) * HD_ + c4];
    }

    float m[8], l[8];
    float4 o[8];
#pragma unroll
    for (int i = 0; i < 8; i++) {
        m[i] = -1e30f; l[i] = 0.f;
        o[i] = make_float4(0.f, 0.f, 0.f, 0.f);
    }

    const int nkt = qbase / KT + 2;

    for (int kt = 0; kt < nkt; kt++) {
        const int kb = kt * KT;
        __syncthreads();
        {
            const int r  = tid >> 4;
            const int c4 = (tid & 15) * 4;
#pragma unroll
            for (int p = 0; p < 4; p++) {
                const int row = r + p * 16;
                float4 kv = *(const float4*)&kptr[(size_t)(kb + row) * HD_ + c4];
                sKT[(c4 + 0) * 68 + row] = kv.x;
                sKT[(c4 + 1) * 68 + row] = kv.y;
                sKT[(c4 + 2) * 68 + row] = kv.z;
                sKT[(c4 + 3) * 68 + row] = kv.w;
                *(float4*)&sV[row * HD_ + c4] =
                    *(const float4*)&vptr[(size_t)(kb + row) * HD_ + c4];
            }
        }
        __syncthreads();

        float s[8][4];
#pragma unroll
        for (int i = 0; i < 8; i++)
#pragma unroll
            for (int j = 0; j < 4; j++) s[i][j] = 0.f;

#pragma unroll
        for (int d4 = 0; d4 < HD_; d4 += 4) {
            float kjf[16];
#pragma unroll
            for (int dd = 0; dd < 4; dd++)
                *(float4*)&kjf[dd * 4] = *(const float4*)&sKT[(d4 + dd) * 68 + tx * 4];
#pragma unroll
            for (int i = 0; i < 8; i++) {
                float qvf[4];
                *(float4*)&qvf[0] = *(const float4*)&sQ[(ty * 8 + i) * HD_ + d4];
#pragma unroll
                for (int dd = 0; dd < 4; dd++)
#pragma unroll
                    for (int j = 0; j < 4; j++)
                        s[i][j] = fmaf(qvf[dd], kjf[dd * 4 + j], s[i][j]);
            }
        }

#pragma unroll
        for (int i = 0; i < 8; i++) {
            const int gq = qbase + ty * 8 + i;
#pragma unroll
            for (int j = 0; j < 4; j++) {
                const int gk = kb + tx * 4 + j;
                s[i][j] = (gk <= gq) ? s[i][j] * SCALE_ : -1e30f;
            }
        }

#pragma unroll
        for (int i = 0; i < 8; i++) {
            float mx = fmaxf(fmaxf(s[i][0], s[i][1]), fmaxf(s[i][2], s[i][3]));
#pragma unroll
            for (int off = 8; off >= 1; off >>= 1)
                mx = fmaxf(mx, __shfl_xor_sync(0xffffffffu, mx, off));
            const float mnew = fmaxf(m[i], mx);
            const float corr = __expf(m[i] - mnew);
            float sum = 0.f;
#pragma unroll
            for (int j = 0; j < 4; j++) {
                const float p = __expf(s[i][j] - mnew);
                s[i][j] = p;
                sum += p;
            }
#pragma unroll
            for (int off = 8; off >= 1; off >>= 1)
                sum += __shfl_xor_sync(0xffffffffu, sum, off);
            l[i] = l[i] * corr + sum;
            m[i] = mnew;
            o[i].x *= corr; o[i].y *= corr; o[i].z *= corr; o[i].w *= corr;
            *(float4*)&sP[(ty * 8 + i) * 68 + tx * 4] =
                make_float4(s[i][0], s[i][1], s[i][2], s[i][3]);
        }
        __syncthreads();

#pragma unroll
        for (int c4 = 0; c4 < KT; c4 += 4) {
            float4 vr[4];
#pragma unroll
            for (int j = 0; j < 4; j++)
                vr[j] = *(const float4*)&sV[(c4 + j) * HD_ + tx * 4];
#pragma unroll
            for (int i = 0; i < 8; i++) {
                float pvf[4];
                *(float4*)&pvf[0] = *(const float4*)&sP[(ty * 8 + i) * 68 + c4];
#pragma unroll
                for (int j = 0; j < 4; j++) {
                    o[i].x = fmaf(pvf[j], vr[j].x, o[i].x);
                    o[i].y = fmaf(pvf[j], vr[j].y, o[i].y);
                    o[i].z = fmaf(pvf[j], vr[j].z, o[i].z);
                    o[i].w = fmaf(pvf[j], vr[j].w, o[i].w);
                }
            }
        }
    }

#pragma unroll
    for (int i = 0; i < 8; i++) {
        const float inv = 1.f / l[i];
        const int t = qbase + ty * 8 + i;
        float4 res = make_float4(o[i].x * inv, o[i].y * inv, o[i].z * inv, o[i].w * inv);
        *(float4*)&g_att[((size_t)(b * T_ + t)) * D_ + h * HD_ + tx * 4] = res;
    }
}

// ======================================================================
extern "C" void kernel_launch(void* const* d_in, const int* in_sizes, int n_in,
                              void* d_out, int out_size)
{
    const float* x      = (const float*)d_in[0];
    const float* W_qkv  = (const float*)d_in[1];
    const float* b_qkv  = (const float*)d_in[2];
    const float* W_out  = (const float*)d_in[3];
    const float* b_out  = (const float*)d_in[4];
    float* out = (float*)d_out;

    __nv_bfloat16 *xh, *xl, *ah, *al, *wqh, *wql, *woh, *wol;
    float* gatt;
    cudaGetSymbolAddress((void**)&xh,  g_xh);
    cudaGetSymbolAddress((void**)&xl,  g_xl);
    cudaGetSymbolAddress((void**)&ah,  g_ah);
    cudaGetSymbolAddress((void**)&al,  g_al);
    cudaGetSymbolAddress((void**)&wqh, g_wqh);
    cudaGetSymbolAddress((void**)&wql, g_wql);
    cudaGetSymbolAddress((void**)&woh, g_woh);
    cudaGetSymbolAddress((void**)&wol, g_wol);
    cudaGetSymbolAddress((void**)&gatt, g_att);

    cudaFuncSetAttribute(gemm_tc_mma, cudaFuncAttributeMaxDynamicSharedMemorySize, SMEM_GT);

    const int nX = B_ * T_ * D_;

    // conversions
    conv_split<<<(nX + 255) / 256, 256>>>(x, xh, xl, nX);
    conv_split_tr<<<(D_ * 3 * D_ + 255) / 256, 256>>>(W_qkv, wqh, wql, D_, 3 * D_);
    conv_split_tr<<<(D_ * D_ + 255) / 256, 256>>>(W_out, woh, wol, D_, D_);

    // 1) QKV projection -> g_q/g_k/g_v
    {
        dim3 grid((3 * D_) / 128, (B_ * T_) / 128);
        gemm_tc_mma<<<grid, 256, SMEM_GT>>>(xh, xl, wqh, wql, b_qkv, nullptr,
                                            B_ * T_, 3 * D_, D_, 0);
    }

    // 2) causal flash attention -> g_att
    {
        const size_t smem = (size_t)(QT * HD_ + HD_ * 68 + KT * HD_ + QT * 68) * sizeof(float);
        cudaFuncSetAttribute(attn_kernel,
                             cudaFuncAttributeMaxDynamicSharedMemorySize, (int)smem);
        dim3 grid(T_ / QT, H_, B_);
        attn_kernel<<<grid, 256, smem>>>();
    }

    // 3) output projection -> d_out
    conv_split<<<(nX + 255) / 256, 256>>>(gatt, ah, al, nX);
    {
        dim3 grid(D_ / 128, (B_ * T_) / 128);
        gemm_tc_mma<<<grid, 256, SMEM_GT>>>(ah, al, woh, wol, b_out, out,
                                            B_ * T_, D_, D_, 1);
    }
}

// round 4
// speedup vs baseline: 1.9249x; 1.6825x over previous
#include <cuda_runtime.h>
#include <cuda_bf16.h>
#include <cstdint>

#define B_   2
#define T_   4096
#define D_   768
#define H_   12
#define HD_  64
#define SCALE_ 0.125f

#define QT 128     // attention q-tile rows
#define KT 64      // attention k-tile cols

// ---------------- scratch (static device allocations) ----------------
// bf16 split q/k/v [B,H,T,hd]
__device__ __nv_bfloat16 g_qh[(size_t)B_ * H_ * T_ * HD_];
__device__ __nv_bfloat16 g_ql[(size_t)B_ * H_ * T_ * HD_];
__device__ __nv_bfloat16 g_kh[(size_t)B_ * H_ * T_ * HD_];
__device__ __nv_bfloat16 g_kl[(size_t)B_ * H_ * T_ * HD_];
__device__ __nv_bfloat16 g_vh[(size_t)B_ * H_ * T_ * HD_];
__device__ __nv_bfloat16 g_vl[(size_t)B_ * H_ * T_ * HD_];
// bf16 split activations / weights
__device__ __nv_bfloat16 g_xh[(size_t)B_ * T_ * D_];
__device__ __nv_bfloat16 g_xl[(size_t)B_ * T_ * D_];
__device__ __nv_bfloat16 g_ah[(size_t)B_ * T_ * D_];   // attention out split
__device__ __nv_bfloat16 g_al[(size_t)B_ * T_ * D_];
__device__ __nv_bfloat16 g_wqh[(size_t)3 * D_ * D_];   // W_qkv^T [2304][768]
__device__ __nv_bfloat16 g_wql[(size_t)3 * D_ * D_];
__device__ __nv_bfloat16 g_woh[(size_t)D_ * D_];       // W_out^T [768][768]
__device__ __nv_bfloat16 g_wol[(size_t)D_ * D_];

// ======================= helpers ========================
__device__ __forceinline__ uint32_t smem_u32(const void* p) {
    uint32_t a;
    asm("{ .reg .u64 t; cvta.to.shared.u64 t, %1; cvt.u32.u64 %0, t; }"
        : "=r"(a) : "l"(p));
    return a;
}

__device__ __forceinline__ void cp16(uint32_t s, const void* g) {
    asm volatile("cp.async.cg.shared.global [%0], [%1], 16;" :: "r"(s), "l"(g));
}
#define CP_COMMIT() asm volatile("cp.async.commit_group;" ::: "memory")
#define CP_WAIT1()  asm volatile("cp.async.wait_group 1;" ::: "memory")
#define CP_WAIT0()  asm volatile("cp.async.wait_group 0;" ::: "memory")

// bf16 HMMA m16n8k16, fp32 accumulate (arch-generic tensor path)
__device__ __forceinline__ void mma16816(float* c, const uint32_t* a, const uint32_t* b) {
    asm volatile(
        "mma.sync.aligned.m16n8k16.row.col.f32.bf16.bf16.f32 "
        "{%0,%1,%2,%3}, {%4,%5,%6,%7}, {%8,%9}, {%0,%1,%2,%3};"
        : "+f"(c[0]), "+f"(c[1]), "+f"(c[2]), "+f"(c[3])
        : "r"(a[0]), "r"(a[1]), "r"(a[2]), "r"(a[3]), "r"(b[0]), "r"(b[1]));
}

__device__ __forceinline__ uint32_t pack_bf(__nv_bfloat16 a, __nv_bfloat16 b) {
    __nv_bfloat162 t(a, b);
    return *reinterpret_cast<uint32_t*>(&t);
}

// split (v0,v1) into packed bf16 hi pair + lo (residual) pair
__device__ __forceinline__ void split2(float v0, float v1, uint32_t& hi, uint32_t& lo) {
    __nv_bfloat16 h0 = __float2bfloat16_rn(v0);
    __nv_bfloat16 h1 = __float2bfloat16_rn(v1);
    float r0 = v0 - __bfloat162float(h0);
    float r1 = v1 - __bfloat162float(h1);
    hi = pack_bf(h0, h1);
    lo = pack_bf(__float2bfloat16_rn(r0), __float2bfloat16_rn(r1));
}

// ======================================================================
// conversions
// ======================================================================
__global__ void conv_split(const float* __restrict__ in,
                           __nv_bfloat16* __restrict__ oh,
                           __nv_bfloat16* __restrict__ ol, int n)
{
    int i = blockIdx.x * blockDim.x + threadIdx.x;
    if (i >= n) return;
    float v = in[i];
    __nv_bfloat16 h = __float2bfloat16_rn(v);
    float r = v - __bfloat162float(h);
    oh[i] = h;
    ol[i] = __float2bfloat16_rn(r);
}

__global__ void conv_split_tr(const float* __restrict__ in,
                              __nv_bfloat16* __restrict__ oh,
                              __nv_bfloat16* __restrict__ ol, int K, int N)
{
    int i = blockIdx.x * blockDim.x + threadIdx.x;
    if (i >= K * N) return;
    int k = i / N, n = i % N;
    float v = in[i];
    __nv_bfloat16 h = __float2bfloat16_rn(v);
    float r = v - __bfloat162float(h);
    oh[(size_t)n * K + k] = h;
    ol[(size_t)n * K + k] = __float2bfloat16_rn(r);
}

// ======================================================================
// HMMA GEMM, bf16 split (hi*hi + hi*lo + lo*hi), C = A @ B_stored^T + bias
// mode 0: split-write into g_{q,k,v}{h,l}; mode 1: fp32 row-major Cout.
// ======================================================================
#define LDK 72
#define TILE_B (128 * LDK * 2)
#define TOFF(buf, t) (((buf) * 4 + (t)) * TILE_B)
#define SMEM_GT (2 * 4 * TILE_B)

__global__ void __launch_bounds__(256, 1) gemm_tc_mma(
    const __nv_bfloat16* __restrict__ Ah, const __nv_bfloat16* __restrict__ Al,
    const __nv_bfloat16* __restrict__ Bh, const __nv_bfloat16* __restrict__ Bl,
    const float* __restrict__ bias, float* __restrict__ Cout,
    int M, int N, int K, int mode)
{
    extern __shared__ char smc[];
    const uint32_t sbase = smem_u32(smc);
    const int tid  = threadIdx.x;
    const int lane = tid & 31;
    const int wid  = tid >> 5;
    const int wm   = wid & 3;
    const int wn   = wid >> 2;
    const int bm = blockIdx.y * 128;
    const int bn = blockIdx.x * 128;

    const char* gA[2] = { (const char*)(Ah + (size_t)bm * K),
                          (const char*)(Al + (size_t)bm * K) };
    const char* gB[2] = { (const char*)(Bh + (size_t)bn * K),
                          (const char*)(Bl + (size_t)bn * K) };

    const int nk = K / 64;

    auto issue_chunk = [&](int k0, int buf) {
#pragma unroll
        for (int t = 0; t < 4; t++) {
            const char* src = (t < 2) ? gA[t] : gB[t - 2];
#pragma unroll
            for (int j = 0; j < 4; j++) {
                const int idx = tid * 4 + j;
                const int row = idx >> 3;
                const int c16 = idx & 7;
                cp16(sbase + TOFF(buf, t) + row * (LDK * 2) + c16 * 16,
                     src + (size_t)row * (K * 2) + k0 * 2 + c16 * 16);
            }
        }
    };

    issue_chunk(0, 0); CP_COMMIT();
    if (nk > 1) { issue_chunk(64, 1); }
    CP_COMMIT();

    float acc[2][8][4];
#pragma unroll
    for (int i = 0; i < 2; i++)
#pragma unroll
        for (int j = 0; j < 8; j++)
#pragma unroll
            for (int q = 0; q < 4; q++) acc[i][j][q] = 0.f;

    const int lr = lane >> 2;
    const int lc = (lane & 3) * 2;

    for (int it = 0; it < nk; ++it) {
        const int buf = it & 1;
        CP_WAIT1();
        __syncthreads();

        const char* sA[2] = { smc + TOFF(buf, 0), smc + TOFF(buf, 1) };
        const char* sB[2] = { smc + TOFF(buf, 2), smc + TOFF(buf, 3) };

#pragma unroll
        for (int kk = 0; kk < 4; kk++) {
            const int kb = kk * 32 + lc * 2;
            uint32_t af[2][2][4];
#pragma unroll
            for (int v = 0; v < 2; v++)
#pragma unroll
                for (int i = 0; i < 2; i++) {
                    const int r0 = (wm * 32 + i * 16 + lr) * (LDK * 2);
                    af[v][i][0] = *(const uint32_t*)(sA[v] + r0 + kb);
                    af[v][i][1] = *(const uint32_t*)(sA[v] + r0 + 8 * (LDK * 2) + kb);
                    af[v][i][2] = *(const uint32_t*)(sA[v] + r0 + kb + 16);
                    af[v][i][3] = *(const uint32_t*)(sA[v] + r0 + 8 * (LDK * 2) + kb + 16);
                }
            uint32_t bf[2][8][2];
#pragma unroll
            for (int v = 0; v < 2; v++)
#pragma unroll
                for (int j = 0; j < 8; j++) {
                    const int n0 = (wn * 64 + j * 8 + lr) * (LDK * 2);
                    bf[v][j][0] = *(const uint32_t*)(sB[v] + n0 + kb);
                    bf[v][j][1] = *(const uint32_t*)(sB[v] + n0 + kb + 16);
                }
#pragma unroll
            for (int i = 0; i < 2; i++)
#pragma unroll
                for (int j = 0; j < 8; j++) {
                    mma16816(acc[i][j], af[0][i], bf[0][j]);
                    mma16816(acc[i][j], af[0][i], bf[1][j]);
                    mma16816(acc[i][j], af[1][i], bf[0][j]);
                }
        }
        __syncthreads();
        if (it + 2 < nk) { issue_chunk((it + 2) * 64, buf); }
        CP_COMMIT();
    }

    // -------- epilogue --------
#pragma unroll
    for (int i = 0; i < 2; i++) {
        const int row0 = bm + wm * 32 + i * 16 + lr;
#pragma unroll
        for (int j = 0; j < 8; j++) {
            const int col = bn + wn * 64 + j * 8 + lc;
            const float b0 = bias[col], b1 = bias[col + 1];
            const float v00 = acc[i][j][0] + b0, v01 = acc[i][j][1] + b1;
            const float v10 = acc[i][j][2] + b0, v11 = acc[i][j][3] + b1;
            if (mode == 1) {
                *(float2*)&Cout[(size_t)row0 * N + col]       = make_float2(v00, v01);
                *(float2*)&Cout[(size_t)(row0 + 8) * N + col] = make_float2(v10, v11);
            } else {
                const int sel = col / D_;
                const int rem = col % D_;
                const int h   = rem / HD_;
                const int d0  = rem % HD_;
                __nv_bfloat16* dh = (sel == 0) ? g_qh : ((sel == 1) ? g_kh : g_vh);
                __nv_bfloat16* dl = (sel == 0) ? g_ql : ((sel == 1) ? g_kl : g_vl);
                const int bb0 = row0 >> 12, t0 = row0 & (T_ - 1);
                const int bb1 = (row0 + 8) >> 12, t1 = (row0 + 8) & (T_ - 1);
                uint32_t hi, lo;
                split2(v00, v01, hi, lo);
                size_t off = ((size_t)(bb0 * H_ + h) * T_ + t0) * HD_ + d0;
                *(uint32_t*)&dh[off] = hi; *(uint32_t*)&dl[off] = lo;
                split2(v10, v11, hi, lo);
                off = ((size_t)(bb1 * H_ + h) * T_ + t1) * HD_ + d0;
                *(uint32_t*)&dh[off] = hi; *(uint32_t*)&dl[off] = lo;
            }
        }
    }
    CP_WAIT0();
}

// ======================================================================
// Causal flash attention on HMMA, bf16 split everywhere.
// Block = (qtile=128, h, b), 256 threads, 8 warps = 8 M-tiles of 16 rows.
// smem: Qh/Ql[128][72], Kh/Kl[64][72], VTh/VTl[64][72] (bf16)  = 73728 B
// ======================================================================
#define AP  72
#define APB (AP * 2)
#define SMEM_AT (128 * APB * 2 + 64 * APB * 4)

__global__ void __launch_bounds__(256, 1) attn_mma()
{
    extern __shared__ char sm[];
    char* sQh = sm;
    char* sQl = sm + 128 * APB;
    char* sKh = sQl + 128 * APB;
    char* sKl = sKh + 64 * APB;
    char* sVh = sKl + 64 * APB;
    char* sVl = sVh + 64 * APB;

    const int tid = threadIdx.x, lane = tid & 31, wid = tid >> 5;
    const int lr = lane >> 2, lq = lane & 3;
    const int qi = (int)gridDim.x - 1 - (int)blockIdx.x;
    const int h = blockIdx.y, b = blockIdx.z;
    const int qbase = qi * QT;

    const size_t bh = (size_t)(b * H_ + h) * T_;
    const char* qh = (const char*)(g_qh + (bh + qbase) * HD_);
    const char* ql = (const char*)(g_ql + (bh + qbase) * HD_);
    const char* kh = (const char*)(g_kh + bh * HD_);
    const char* kl = (const char*)(g_kl + bh * HD_);
    const char* vh = (const char*)(g_vh + bh * HD_);
    const char* vl = (const char*)(g_vl + bh * HD_);

    // stage Q (hi/lo), rows of 128 bytes
#pragma unroll
    for (int p = 0; p < 4; p++) {
        const int idx = p * 256 + tid;
        const int row = idx >> 3, c16 = idx & 7;
        *(uint4*)(sQh + row * APB + c16 * 16) =
            *(const uint4*)(qh + (size_t)row * 128 + c16 * 16);
        *(uint4*)(sQl + row * APB + c16 * 16) =
            *(const uint4*)(ql + (size_t)row * 128 + c16 * 16);
    }

    float m[2] = {-1e30f, -1e30f}, l[2] = {0.f, 0.f};
    float o[8][4];
#pragma unroll
    for (int j = 0; j < 8; j++)
#pragma unroll
        for (int q = 0; q < 4; q++) o[j][q] = 0.f;

    const int nkt = qbase / KT + 2;
    const int rowmaxw = qbase + wid * 16 + 15;   // max row this warp owns

    for (int kt = 0; kt < nkt; kt++) {
        const int kb = kt * KT;
        __syncthreads();
        // stage K (natural layout = B operand for S)
#pragma unroll
        for (int p = 0; p < 2; p++) {
            const int idx = p * 256 + tid;
            const int row = idx >> 3, c16 = idx & 7;
            *(uint4*)(sKh + row * APB + c16 * 16) =
                *(const uint4*)(kh + (size_t)(kb + row) * 128 + c16 * 16);
            *(uint4*)(sKl + row * APB + c16 * 16) =
                *(const uint4*)(kl + (size_t)(kb + row) * 128 + c16 * 16);
        }
        // stage V transposed: [hd][key]
#pragma unroll
        for (int p = 0; p < 8; p++) {
            const int idx = p * 256 + tid;
            const int key = idx >> 5, hd2 = idx & 31;
            uint32_t wv = *(const uint32_t*)(vh + (size_t)(kb + key) * 128 + hd2 * 4);
            *(uint16_t*)(sVh + (2 * hd2) * APB + key * 2)     = (uint16_t)(wv & 0xffff);
            *(uint16_t*)(sVh + (2 * hd2 + 1) * APB + key * 2) = (uint16_t)(wv >> 16);
            uint32_t wl = *(const uint32_t*)(vl + (size_t)(kb + key) * 128 + hd2 * 4);
            *(uint16_t*)(sVl + (2 * hd2) * APB + key * 2)     = (uint16_t)(wl & 0xffff);
            *(uint16_t*)(sVl + (2 * hd2 + 1) * APB + key * 2) = (uint16_t)(wl >> 16);
        }
        __syncthreads();

        if (kb > rowmaxw) continue;   // tile entirely in the future for this warp

        // ---- S = Q K^T (split) ----
        float s[8][4];
#pragma unroll
        for (int j = 0; j < 8; j++)
#pragma unroll
            for (int q = 0; q < 4; q++) s[j][q] = 0.f;

        const int r0 = (wid * 16 + lr) * APB;
#pragma unroll
        for (int kk = 0; kk < 4; kk++) {
            const int kbo = kk * 32 + lq * 4;
            uint32_t ah[4], al[4];
            ah[0] = *(const uint32_t*)(sQh + r0 + kbo);
            ah[1] = *(const uint32_t*)(sQh + r0 + 8 * APB + kbo);
            ah[2] = *(const uint32_t*)(sQh + r0 + kbo + 16);
            ah[3] = *(const uint32_t*)(sQh + r0 + 8 * APB + kbo + 16);
            al[0] = *(const uint32_t*)(sQl + r0 + kbo);
            al[1] = *(const uint32_t*)(sQl + r0 + 8 * APB + kbo);
            al[2] = *(const uint32_t*)(sQl + r0 + kbo + 16);
            al[3] = *(const uint32_t*)(sQl + r0 + 8 * APB + kbo + 16);
#pragma unroll
            for (int j = 0; j < 8; j++) {
                const int n0 = (j * 8 + lr) * APB;
                uint32_t bh2[2] = { *(const uint32_t*)(sKh + n0 + kbo),
                                    *(const uint32_t*)(sKh + n0 + kbo + 16) };
                uint32_t bl2[2] = { *(const uint32_t*)(sKl + n0 + kbo),
                                    *(const uint32_t*)(sKl + n0 + kbo + 16) };
                mma16816(s[j], ah, bh2);
                mma16816(s[j], ah, bl2);
                mma16816(s[j], al, bh2);
            }
        }

        // ---- scale + causal mask ----
        const bool needmask = (kb + 63) > (qbase + wid * 16);
        if (needmask) {
            const int row_a = qbase + wid * 16 + lr;
#pragma unroll
            for (int j = 0; j < 8; j++) {
                const int col0 = kb + j * 8 + lq * 2;
                s[j][0] = (col0     <= row_a)     ? s[j][0] * SCALE_ : -1e30f;
                s[j][1] = (col0 + 1 <= row_a)     ? s[j][1] * SCALE_ : -1e30f;
                s[j][2] = (col0     <= row_a + 8) ? s[j][2] * SCALE_ : -1e30f;
                s[j][3] = (col0 + 1 <= row_a + 8) ? s[j][3] * SCALE_ : -1e30f;
            }
        } else {
#pragma unroll
            for (int j = 0; j < 8; j++)
#pragma unroll
                for (int q = 0; q < 4; q++) s[j][q] *= SCALE_;
        }

        // ---- online softmax (rows lr, lr+8) ----
#pragma unroll
        for (int r = 0; r < 2; r++) {
            float mx = -1e30f;
#pragma unroll
            for (int j = 0; j < 8; j++)
                mx = fmaxf(mx, fmaxf(s[j][2 * r], s[j][2 * r + 1]));
            mx = fmaxf(mx, __shfl_xor_sync(0xffffffffu, mx, 1));
            mx = fmaxf(mx, __shfl_xor_sync(0xffffffffu, mx, 2));
            const float mnew = fmaxf(m[r], mx);
            const float corr = __expf(m[r] - mnew);
            float sum = 0.f;
#pragma unroll
            for (int j = 0; j < 8; j++) {
                const float p0 = __expf(s[j][2 * r]     - mnew);
                const float p1 = __expf(s[j][2 * r + 1] - mnew);
                s[j][2 * r] = p0; s[j][2 * r + 1] = p1;
                sum += p0 + p1;
            }
            sum += __shfl_xor_sync(0xffffffffu, sum, 1);
            sum += __shfl_xor_sync(0xffffffffu, sum, 2);
            l[r] = l[r] * corr + sum;
            m[r] = mnew;
#pragma unroll
            for (int j = 0; j < 8; j++) {
                o[j][2 * r] *= corr; o[j][2 * r + 1] *= corr;
            }
        }

        // ---- P fragments (split) ----
        uint32_t ph0[8], ph1[8], pl0[8], pl1[8];
#pragma unroll
        for (int j = 0; j < 8; j++) {
            split2(s[j][0], s[j][1], ph0[j], pl0[j]);
            split2(s[j][2], s[j][3], ph1[j], pl1[j]);
        }

        // ---- O += P V (split) ----
#pragma unroll
        for (int kk = 0; kk < 4; kk++) {
            uint32_t a_h[4] = { ph0[2 * kk], ph1[2 * kk], ph0[2 * kk + 1], ph1[2 * kk + 1] };
            uint32_t a_l[4] = { pl0[2 * kk], pl1[2 * kk], pl0[2 * kk + 1], pl1[2 * kk + 1] };
            const int kbo = kk * 32 + lq * 4;
#pragma unroll
            for (int jn = 0; jn < 8; jn++) {
                const int n0 = (jn * 8 + lr) * APB;
                uint32_t bh2[2] = { *(const uint32_t*)(sVh + n0 + kbo),
                                    *(const uint32_t*)(sVh + n0 + kbo + 16) };
                uint32_t bl2[2] = { *(const uint32_t*)(sVl + n0 + kbo),
                                    *(const uint32_t*)(sVl + n0 + kbo + 16) };
                mma16816(o[jn], a_h, bh2);
                mma16816(o[jn], a_h, bl2);
                mma16816(o[jn], a_l, bh2);
            }
        }
    }

    // ---- epilogue: normalize, split-write to g_ah/g_al [B,T,D] ----
    const float inv0 = 1.f / l[0], inv1 = 1.f / l[1];
    const int t0 = qbase + wid * 16 + lr;
    const int t1 = t0 + 8;
#pragma unroll
    for (int jn = 0; jn < 8; jn++) {
        const int d = h * HD_ + jn * 8 + lq * 2;
        uint32_t hi, lo;
        split2(o[jn][0] * inv0, o[jn][1] * inv0, hi, lo);
        size_t off = (size_t)(b * T_ + t0) * D_ + d;
        *(uint32_t*)&g_ah[off] = hi; *(uint32_t*)&g_al[off] = lo;
        split2(o[jn][2] * inv1, o[jn][3] * inv1, hi, lo);
        off = (size_t)(b * T_ + t1) * D_ + d;
        *(uint32_t*)&g_ah[off] = hi; *(uint32_t*)&g_al[off] = lo;
    }
}

// ======================================================================
extern "C" void kernel_launch(void* const* d_in, const int* in_sizes, int n_in,
                              void* d_out, int out_size)
{
    const float* x      = (const float*)d_in[0];
    const float* W_qkv  = (const float*)d_in[1];
    const float* b_qkv  = (const float*)d_in[2];
    const float* W_out  = (const float*)d_in[3];
    const float* b_out  = (const float*)d_in[4];
    float* out = (float*)d_out;

    __nv_bfloat16 *xh, *xl, *ah, *al, *wqh, *wql, *woh, *wol;
    cudaGetSymbolAddress((void**)&xh,  g_xh);
    cudaGetSymbolAddress((void**)&xl,  g_xl);
    cudaGetSymbolAddress((void**)&ah,  g_ah);
    cudaGetSymbolAddress((void**)&al,  g_al);
    cudaGetSymbolAddress((void**)&wqh, g_wqh);
    cudaGetSymbolAddress((void**)&wql, g_wql);
    cudaGetSymbolAddress((void**)&woh, g_woh);
    cudaGetSymbolAddress((void**)&wol, g_wol);

    cudaFuncSetAttribute(gemm_tc_mma, cudaFuncAttributeMaxDynamicSharedMemorySize, SMEM_GT);
    cudaFuncSetAttribute(attn_mma,    cudaFuncAttributeMaxDynamicSharedMemorySize, SMEM_AT);

    const int nX = B_ * T_ * D_;

    // conversions
    conv_split<<<(nX + 255) / 256, 256>>>(x, xh, xl, nX);
    conv_split_tr<<<(D_ * 3 * D_ + 255) / 256, 256>>>(W_qkv, wqh, wql, D_, 3 * D_);
    conv_split_tr<<<(D_ * D_ + 255) / 256, 256>>>(W_out, woh, wol, D_, D_);

    // 1) QKV projection -> split q/k/v
    {
        dim3 grid((3 * D_) / 128, (B_ * T_) / 128);
        gemm_tc_mma<<<grid, 256, SMEM_GT>>>(xh, xl, wqh, wql, b_qkv, nullptr,
                                            B_ * T_, 3 * D_, D_, 0);
    }

    // 2) causal flash attention (HMMA) -> split g_ah/g_al
    {
        dim3 grid(T_ / QT, H_, B_);
        attn_mma<<<grid, 256, SMEM_AT>>>();
    }

    // 3) output projection -> d_out
    {
        dim3 grid(D_ / 128, (B_ * T_) / 128);
        gemm_tc_mma<<<grid, 256, SMEM_GT>>>(ah, al, woh, wol, b_out, out,
                                            B_ * T_, D_, D_, 1);
    }
}

// round 5
// speedup vs baseline: 1.9262x; 1.0007x over previous
#include <cuda_runtime.h>
#include <cuda_bf16.h>
#include <cstdint>

#define B_   2
#define T_   4096
#define D_   768
#define H_   12
#define HD_  64
#define SCALE_ 0.125f

#define QT 128     // attention q-tile rows
#define KT 64      // attention k-tile cols

// ---------------- scratch (static device allocations) ----------------
__device__ __nv_bfloat16 g_qh[(size_t)B_ * H_ * T_ * HD_];
__device__ __nv_bfloat16 g_ql[(size_t)B_ * H_ * T_ * HD_];
__device__ __nv_bfloat16 g_kh[(size_t)B_ * H_ * T_ * HD_];
__device__ __nv_bfloat16 g_kl[(size_t)B_ * H_ * T_ * HD_];
__device__ __nv_bfloat16 g_vh[(size_t)B_ * H_ * T_ * HD_];
__device__ __nv_bfloat16 g_vl[(size_t)B_ * H_ * T_ * HD_];
__device__ __nv_bfloat16 g_xh[(size_t)B_ * T_ * D_];
__device__ __nv_bfloat16 g_xl[(size_t)B_ * T_ * D_];
__device__ __nv_bfloat16 g_ah[(size_t)B_ * T_ * D_];
__device__ __nv_bfloat16 g_al[(size_t)B_ * T_ * D_];
__device__ __nv_bfloat16 g_wqh[(size_t)3 * D_ * D_];
__device__ __nv_bfloat16 g_wql[(size_t)3 * D_ * D_];
__device__ __nv_bfloat16 g_woh[(size_t)D_ * D_];
__device__ __nv_bfloat16 g_wol[(size_t)D_ * D_];

// ======================= helpers ========================
__device__ __forceinline__ uint32_t smem_u32(const void* p) {
    uint32_t a;
    asm("{ .reg .u64 t; cvta.to.shared.u64 t, %1; cvt.u32.u64 %0, t; }"
        : "=r"(a) : "l"(p));
    return a;
}

__device__ __forceinline__ void cp16(uint32_t s, const void* g) {
    asm volatile("cp.async.cg.shared.global [%0], [%1], 16;" :: "r"(s), "l"(g));
}
#define CP_COMMIT() asm volatile("cp.async.commit_group;" ::: "memory")
#define CP_WAIT1()  asm volatile("cp.async.wait_group 1;" ::: "memory")
#define CP_WAIT0()  asm volatile("cp.async.wait_group 0;" ::: "memory")

// bf16 HMMA m16n8k16, fp32 accumulate. NOT volatile: let ptxas schedule.
__device__ __forceinline__ void mma16816(float* c, const uint32_t* a, const uint32_t* b) {
    asm("mma.sync.aligned.m16n8k16.row.col.f32.bf16.bf16.f32 "
        "{%0,%1,%2,%3}, {%4,%5,%6,%7}, {%8,%9}, {%0,%1,%2,%3};"
        : "+f"(c[0]), "+f"(c[1]), "+f"(c[2]), "+f"(c[3])
        : "r"(a[0]), "r"(a[1]), "r"(a[2]), "r"(a[3]), "r"(b[0]), "r"(b[1]));
}

__device__ __forceinline__ uint32_t pack_bf(__nv_bfloat16 a, __nv_bfloat16 b) {
    __nv_bfloat162 t(a, b);
    return *reinterpret_cast<uint32_t*>(&t);
}

__device__ __forceinline__ void split2(float v0, float v1, uint32_t& hi, uint32_t& lo) {
    __nv_bfloat16 h0 = __float2bfloat16_rn(v0);
    __nv_bfloat16 h1 = __float2bfloat16_rn(v1);
    float r0 = v0 - __bfloat162float(h0);
    float r1 = v1 - __bfloat162float(h1);
    hi = pack_bf(h0, h1);
    lo = pack_bf(__float2bfloat16_rn(r0), __float2bfloat16_rn(r1));
}

// ======================================================================
// conversions
// ======================================================================
__global__ void conv_split(const float* __restrict__ in,
                           __nv_bfloat16* __restrict__ oh,
                           __nv_bfloat16* __restrict__ ol, int n)
{
    int i = blockIdx.x * blockDim.x + threadIdx.x;
    if (i >= n) return;
    float v = in[i];
    __nv_bfloat16 h = __float2bfloat16_rn(v);
    float r = v - __bfloat162float(h);
    oh[i] = h;
    ol[i] = __float2bfloat16_rn(r);
}

__global__ void conv_split_tr(const float* __restrict__ in,
                              __nv_bfloat16* __restrict__ oh,
                              __nv_bfloat16* __restrict__ ol, int K, int N)
{
    int i = blockIdx.x * blockDim.x + threadIdx.x;
    if (i >= K * N) return;
    int k = i / N, n = i % N;
    float v = in[i];
    __nv_bfloat16 h = __float2bfloat16_rn(v);
    float r = v - __bfloat162float(h);
    oh[(size_t)n * K + k] = h;
    ol[(size_t)n * K + k] = __float2bfloat16_rn(r);
}

// ======================================================================
// HMMA GEMM, bf16 split, product-major MMA issue (independent acc chains)
// ======================================================================
#define LDK 72
#define TILE_B (128 * LDK * 2)
#define TOFF(buf, t) (((buf) * 4 + (t)) * TILE_B)
#define SMEM_GT (2 * 4 * TILE_B)

__global__ void __launch_bounds__(256, 1) gemm_tc_mma(
    const __nv_bfloat16* __restrict__ Ah, const __nv_bfloat16* __restrict__ Al,
    const __nv_bfloat16* __restrict__ Bh, const __nv_bfloat16* __restrict__ Bl,
    const float* __restrict__ bias, float* __restrict__ Cout,
    int M, int N, int K, int mode)
{
    extern __shared__ char smc[];
    const uint32_t sbase = smem_u32(smc);
    const int tid  = threadIdx.x;
    const int lane = tid & 31;
    const int wid  = tid >> 5;
    const int wm   = wid & 3;
    const int wn   = wid >> 2;
    const int bm = blockIdx.y * 128;
    const int bn = blockIdx.x * 128;

    const char* gA[2] = { (const char*)(Ah + (size_t)bm * K),
                          (const char*)(Al + (size_t)bm * K) };
    const char* gB[2] = { (const char*)(Bh + (size_t)bn * K),
                          (const char*)(Bl + (size_t)bn * K) };

    const int nk = K / 64;

    auto issue_chunk = [&](int k0, int buf) {
#pragma unroll
        for (int t = 0; t < 4; t++) {
            const char* src = (t < 2) ? gA[t] : gB[t - 2];
#pragma unroll
            for (int j = 0; j < 4; j++) {
                const int idx = tid * 4 + j;
                const int row = idx >> 3;
                const int c16 = idx & 7;
                cp16(sbase + TOFF(buf, t) + row * (LDK * 2) + c16 * 16,
                     src + (size_t)row * (K * 2) + k0 * 2 + c16 * 16);
            }
        }
    };

    issue_chunk(0, 0); CP_COMMIT();
    if (nk > 1) { issue_chunk(64, 1); }
    CP_COMMIT();

    float acc[2][8][4];
#pragma unroll
    for (int i = 0; i < 2; i++)
#pragma unroll
        for (int j = 0; j < 8; j++)
#pragma unroll
            for (int q = 0; q < 4; q++) acc[i][j][q] = 0.f;

    const int lr = lane >> 2;
    const int lc = (lane & 3) * 2;

    for (int it = 0; it < nk; ++it) {
        const int buf = it & 1;
        CP_WAIT1();
        __syncthreads();

        const char* sA[2] = { smc + TOFF(buf, 0), smc + TOFF(buf, 1) };
        const char* sB[2] = { smc + TOFF(buf, 2), smc + TOFF(buf, 3) };

#pragma unroll
        for (int kk = 0; kk < 4; kk++) {
            const int kb = kk * 32 + lc * 2;
            uint32_t af[2][2][4];
#pragma unroll
            for (int v = 0; v < 2; v++)
#pragma unroll
                for (int i = 0; i < 2; i++) {
                    const int r0 = (wm * 32 + i * 16 + lr) * (LDK * 2);
                    af[v][i][0] = *(const uint32_t*)(sA[v] + r0 + kb);
                    af[v][i][1] = *(const uint32_t*)(sA[v] + r0 + 8 * (LDK * 2) + kb);
                    af[v][i][2] = *(const uint32_t*)(sA[v] + r0 + kb + 16);
                    af[v][i][3] = *(const uint32_t*)(sA[v] + r0 + 8 * (LDK * 2) + kb + 16);
                }
            uint32_t bf[2][8][2];
#pragma unroll
            for (int v = 0; v < 2; v++)
#pragma unroll
                for (int j = 0; j < 8; j++) {
                    const int n0 = (wn * 64 + j * 8 + lr) * (LDK * 2);
                    bf[v][j][0] = *(const uint32_t*)(sB[v] + n0 + kb);
                    bf[v][j][1] = *(const uint32_t*)(sB[v] + n0 + kb + 16);
                }
            // product-major passes: 16 independent accumulators per pass
#pragma unroll
            for (int i = 0; i < 2; i++)
#pragma unroll
                for (int j = 0; j < 8; j++)
                    mma16816(acc[i][j], af[0][i], bf[0][j]);   // hi*hi
#pragma unroll
            for (int i = 0; i < 2; i++)
#pragma unroll
                for (int j = 0; j < 8; j++)
                    mma16816(acc[i][j], af[0][i], bf[1][j]);   // hi*lo
#pragma unroll
            for (int i = 0; i < 2; i++)
#pragma unroll
                for (int j = 0; j < 8; j++)
                    mma16816(acc[i][j], af[1][i], bf[0][j]);   // lo*hi
        }
        __syncthreads();
        if (it + 2 < nk) { issue_chunk((it + 2) * 64, buf); }
        CP_COMMIT();
    }

    // -------- epilogue --------
#pragma unroll
    for (int i = 0; i < 2; i++) {
        const int row0 = bm + wm * 32 + i * 16 + lr;
#pragma unroll
        for (int j = 0; j < 8; j++) {
            const int col = bn + wn * 64 + j * 8 + lc;
            const float b0 = bias[col], b1 = bias[col + 1];
            const float v00 = acc[i][j][0] + b0, v01 = acc[i][j][1] + b1;
            const float v10 = acc[i][j][2] + b0, v11 = acc[i][j][3] + b1;
            if (mode == 1) {
                *(float2*)&Cout[(size_t)row0 * N + col]       = make_float2(v00, v01);
                *(float2*)&Cout[(size_t)(row0 + 8) * N + col] = make_float2(v10, v11);
            } else {
                const int sel = col / D_;
                const int rem = col % D_;
                const int h   = rem / HD_;
                const int d0  = rem % HD_;
                __nv_bfloat16* dh = (sel == 0) ? g_qh : ((sel == 1) ? g_kh : g_vh);
                __nv_bfloat16* dl = (sel == 0) ? g_ql : ((sel == 1) ? g_kl : g_vl);
                const int bb0 = row0 >> 12, t0 = row0 & (T_ - 1);
                const int bb1 = (row0 + 8) >> 12, t1 = (row0 + 8) & (T_ - 1);
                uint32_t hi, lo;
                split2(v00, v01, hi, lo);
                size_t off = ((size_t)(bb0 * H_ + h) * T_ + t0) * HD_ + d0;
                *(uint32_t*)&dh[off] = hi; *(uint32_t*)&dl[off] = lo;
                split2(v10, v11, hi, lo);
                off = ((size_t)(bb1 * H_ + h) * T_ + t1) * HD_ + d0;
                *(uint32_t*)&dh[off] = hi; *(uint32_t*)&dl[off] = lo;
            }
        }
    }
    CP_WAIT0();
}

// ======================================================================
// Causal flash attention on HMMA, bf16 split, product-major MMA issue.
// ======================================================================
#define AP  72
#define APB (AP * 2)
#define SMEM_AT (128 * APB * 2 + 64 * APB * 4)

__global__ void __launch_bounds__(256, 1) attn_mma()
{
    extern __shared__ char sm[];
    char* sQh = sm;
    char* sQl = sm + 128 * APB;
    char* sKh = sQl + 128 * APB;
    char* sKl = sKh + 64 * APB;
    char* sVh = sKl + 64 * APB;
    char* sVl = sVh + 64 * APB;

    const int tid = threadIdx.x, lane = tid & 31, wid = tid >> 5;
    const int lr = lane >> 2, lq = lane & 3;
    const int qi = (int)gridDim.x - 1 - (int)blockIdx.x;
    const int h = blockIdx.y, b = blockIdx.z;
    const int qbase = qi * QT;

    const size_t bh = (size_t)(b * H_ + h) * T_;
    const char* qh = (const char*)(g_qh + (bh + qbase) * HD_);
    const char* ql = (const char*)(g_ql + (bh + qbase) * HD_);
    const char* kh = (const char*)(g_kh + bh * HD_);
    const char* kl = (const char*)(g_kl + bh * HD_);
    const char* vh = (const char*)(g_vh + bh * HD_);
    const char* vl = (const char*)(g_vl + bh * HD_);

#pragma unroll
    for (int p = 0; p < 4; p++) {
        const int idx = p * 256 + tid;
        const int row = idx >> 3, c16 = idx & 7;
        *(uint4*)(sQh + row * APB + c16 * 16) =
            *(const uint4*)(qh + (size_t)row * 128 + c16 * 16);
        *(uint4*)(sQl + row * APB + c16 * 16) =
            *(const uint4*)(ql + (size_t)row * 128 + c16 * 16);
    }

    float m[2] = {-1e30f, -1e30f}, l[2] = {0.f, 0.f};
    float o[8][4];
#pragma unroll
    for (int j = 0; j < 8; j++)
#pragma unroll
        for (int q = 0; q < 4; q++) o[j][q] = 0.f;

    const int nkt = qbase / KT + 2;
    const int rowmaxw = qbase + wid * 16 + 15;

    for (int kt = 0; kt < nkt; kt++) {
        const int kb = kt * KT;
        __syncthreads();
#pragma unroll
        for (int p = 0; p < 2; p++) {
            const int idx = p * 256 + tid;
            const int row = idx >> 3, c16 = idx & 7;
            *(uint4*)(sKh + row * APB + c16 * 16) =
                *(const uint4*)(kh + (size_t)(kb + row) * 128 + c16 * 16);
            *(uint4*)(sKl + row * APB + c16 * 16) =
                *(const uint4*)(kl + (size_t)(kb + row) * 128 + c16 * 16);
        }
#pragma unroll
        for (int p = 0; p < 8; p++) {
            const int idx = p * 256 + tid;
            const int key = idx >> 5, hd2 = idx & 31;
            uint32_t wv = *(const uint32_t*)(vh + (size_t)(kb + key) * 128 + hd2 * 4);
            *(uint16_t*)(sVh + (2 * hd2) * APB + key * 2)     = (uint16_t)(wv & 0xffff);
            *(uint16_t*)(sVh + (2 * hd2 + 1) * APB + key * 2) = (uint16_t)(wv >> 16);
            uint32_t wl = *(const uint32_t*)(vl + (size_t)(kb + key) * 128 + hd2 * 4);
            *(uint16_t*)(sVl + (2 * hd2) * APB + key * 2)     = (uint16_t)(wl & 0xffff);
            *(uint16_t*)(sVl + (2 * hd2 + 1) * APB + key * 2) = (uint16_t)(wl >> 16);
        }
        __syncthreads();

        if (kb > rowmaxw) continue;

        // ---- S = Q K^T (split, product-major) ----
        float s[8][4];
#pragma unroll
        for (int j = 0; j < 8; j++)
#pragma unroll
            for (int q = 0; q < 4; q++) s[j][q] = 0.f;

        const int r0 = (wid * 16 + lr) * APB;
#pragma unroll
        for (int kk = 0; kk < 4; kk++) {
            const int kbo = kk * 32 + lq * 4;
            uint32_t ah[4], al[4];
            ah[0] = *(const uint32_t*)(sQh + r0 + kbo);
            ah[1] = *(const uint32_t*)(sQh + r0 + 8 * APB + kbo);
            ah[2] = *(const uint32_t*)(sQh + r0 + kbo + 16);
            ah[3] = *(const uint32_t*)(sQh + r0 + 8 * APB + kbo + 16);
            al[0] = *(const uint32_t*)(sQl + r0 + kbo);
            al[1] = *(const uint32_t*)(sQl + r0 + 8 * APB + kbo);
            al[2] = *(const uint32_t*)(sQl + r0 + kbo + 16);
            al[3] = *(const uint32_t*)(sQl + r0 + 8 * APB + kbo + 16);
            uint32_t bh2[8][2], bl2[8][2];
#pragma unroll
            for (int j = 0; j < 8; j++) {
                const int n0 = (j * 8 + lr) * APB;
                bh2[j][0] = *(const uint32_t*)(sKh + n0 + kbo);
                bh2[j][1] = *(const uint32_t*)(sKh + n0 + kbo + 16);
                bl2[j][0] = *(const uint32_t*)(sKl + n0 + kbo);
                bl2[j][1] = *(const uint32_t*)(sKl + n0 + kbo + 16);
            }
#pragma unroll
            for (int j = 0; j < 8; j++) mma16816(s[j], ah, bh2[j]);
#pragma unroll
            for (int j = 0; j < 8; j++) mma16816(s[j], ah, bl2[j]);
#pragma unroll
            for (int j = 0; j < 8; j++) mma16816(s[j], al, bh2[j]);
        }

        // ---- scale + causal mask ----
        const bool needmask = (kb + 63) > (qbase + wid * 16);
        if (needmask) {
            const int row_a = qbase + wid * 16 + lr;
#pragma unroll
            for (int j = 0; j < 8; j++) {
                const int col0 = kb + j * 8 + lq * 2;
                s[j][0] = (col0     <= row_a)     ? s[j][0] * SCALE_ : -1e30f;
                s[j][1] = (col0 + 1 <= row_a)     ? s[j][1] * SCALE_ : -1e30f;
                s[j][2] = (col0     <= row_a + 8) ? s[j][2] * SCALE_ : -1e30f;
                s[j][3] = (col0 + 1 <= row_a + 8) ? s[j][3] * SCALE_ : -1e30f;
            }
        } else {
#pragma unroll
            for (int j = 0; j < 8; j++)
#pragma unroll
                for (int q = 0; q < 4; q++) s[j][q] *= SCALE_;
        }

        // ---- online softmax ----
#pragma unroll
        for (int r = 0; r < 2; r++) {
            float mx = -1e30f;
#pragma unroll
            for (int j = 0; j < 8; j++)
                mx = fmaxf(mx, fmaxf(s[j][2 * r], s[j][2 * r + 1]));
            mx = fmaxf(mx, __shfl_xor_sync(0xffffffffu, mx, 1));
            mx = fmaxf(mx, __shfl_xor_sync(0xffffffffu, mx, 2));
            const float mnew = fmaxf(m[r], mx);
            const float corr = __expf(m[r] - mnew);
            float sum = 0.f;
#pragma unroll
            for (int j = 0; j < 8; j++) {
                const float p0 = __expf(s[j][2 * r]     - mnew);
                const float p1 = __expf(s[j][2 * r + 1] - mnew);
                s[j][2 * r] = p0; s[j][2 * r + 1] = p1;
                sum += p0 + p1;
            }
            sum += __shfl_xor_sync(0xffffffffu, sum, 1);
            sum += __shfl_xor_sync(0xffffffffu, sum, 2);
            l[r] = l[r] * corr + sum;
            m[r] = mnew;
#pragma unroll
            for (int j = 0; j < 8; j++) {
                o[j][2 * r] *= corr; o[j][2 * r + 1] *= corr;
            }
        }

        // ---- P fragments (split) ----
        uint32_t ph0[8], ph1[8], pl0[8], pl1[8];
#pragma unroll
        for (int j = 0; j < 8; j++) {
            split2(s[j][0], s[j][1], ph0[j], pl0[j]);
            split2(s[j][2], s[j][3], ph1[j], pl1[j]);
        }

        // ---- O += P V (split, product-major) ----
#pragma unroll
        for (int kk = 0; kk < 4; kk++) {
            uint32_t a_h[4] = { ph0[2 * kk], ph1[2 * kk], ph0[2 * kk + 1], ph1[2 * kk + 1] };
            uint32_t a_l[4] = { pl0[2 * kk], pl1[2 * kk], pl0[2 * kk + 1], pl1[2 * kk + 1] };
            const int kbo = kk * 32 + lq * 4;
            uint32_t vh2[8][2], vl2[8][2];
#pragma unroll
            for (int jn = 0; jn < 8; jn++) {
                const int n0 = (jn * 8 + lr) * APB;
                vh2[jn][0] = *(const uint32_t*)(sVh + n0 + kbo);
                vh2[jn][1] = *(const uint32_t*)(sVh + n0 + kbo + 16);
                vl2[jn][0] = *(const uint32_t*)(sVl + n0 + kbo);
                vl2[jn][1] = *(const uint32_t*)(sVl + n0 + kbo + 16);
            }
#pragma unroll
            for (int jn = 0; jn < 8; jn++) mma16816(o[jn], a_h, vh2[jn]);
#pragma unroll
            for (int jn = 0; jn < 8; jn++) mma16816(o[jn], a_h, vl2[jn]);
#pragma unroll
            for (int jn = 0; jn < 8; jn++) mma16816(o[jn], a_l, vh2[jn]);
        }
    }

    // ---- epilogue ----
    const float inv0 = 1.f / l[0], inv1 = 1.f / l[1];
    const int t0 = qbase + wid * 16 + lr;
    const int t1 = t0 + 8;
#pragma unroll
    for (int jn = 0; jn < 8; jn++) {
        const int d = h * HD_ + jn * 8 + lq * 2;
        uint32_t hi, lo;
        split2(o[jn][0] * inv0, o[jn][1] * inv0, hi, lo);
        size_t off = (size_t)(b * T_ + t0) * D_ + d;
        *(uint32_t*)&g_ah[off] = hi; *(uint32_t*)&g_al[off] = lo;
        split2(o[jn][2] * inv1, o[jn][3] * inv1, hi, lo);
        off = (size_t)(b * T_ + t1) * D_ + d;
        *(uint32_t*)&g_ah[off] = hi; *(uint32_t*)&g_al[off] = lo;
    }
}

// ======================================================================
extern "C" void kernel_launch(void* const* d_in, const int* in_sizes, int n_in,
                              void* d_out, int out_size)
{
    const float* x      = (const float*)d_in[0];
    const float* W_qkv  = (const float*)d_in[1];
    const float* b_qkv  = (const float*)d_in[2];
    const float* W_out  = (const float*)d_in[3];
    const float* b_out  = (const float*)d_in[4];
    float* out = (float*)d_out;

    __nv_bfloat16 *xh, *xl, *ah, *al, *wqh, *wql, *woh, *wol;
    cudaGetSymbolAddress((void**)&xh,  g_xh);
    cudaGetSymbolAddress((void**)&xl,  g_xl);
    cudaGetSymbolAddress((void**)&ah,  g_ah);
    cudaGetSymbolAddress((void**)&al,  g_al);
    cudaGetSymbolAddress((void**)&wqh, g_wqh);
    cudaGetSymbolAddress((void**)&wql, g_wql);
    cudaGetSymbolAddress((void**)&woh, g_woh);
    cudaGetSymbolAddress((void**)&wol, g_wol);

    cudaFuncSetAttribute(gemm_tc_mma, cudaFuncAttributeMaxDynamicSharedMemorySize, SMEM_GT);
    cudaFuncSetAttribute(attn_mma,    cudaFuncAttributeMaxDynamicSharedMemorySize, SMEM_AT);

    const int nX = B_ * T_ * D_;

    conv_split<<<(nX + 255) / 256, 256>>>(x, xh, xl, nX);
    conv_split_tr<<<(D_ * 3 * D_ + 255) / 256, 256>>>(W_qkv, wqh, wql, D_, 3 * D_);
    conv_split_tr<<<(D_ * D_ + 255) / 256, 256>>>(W_out, woh, wol, D_, D_);

    {
        dim3 grid((3 * D_) / 128, (B_ * T_) / 128);
        gemm_tc_mma<<<grid, 256, SMEM_GT>>>(xh, xl, wqh, wql, b_qkv, nullptr,
                                            B_ * T_, 3 * D_, D_, 0);
    }
    {
        dim3 grid(T_ / QT, H_, B_);
        attn_mma<<<grid, 256, SMEM_AT>>>();
    }
    {
        dim3 grid(D_ / 128, (B_ * T_) / 128);
        gemm_tc_mma<<<grid, 256, SMEM_GT>>>(ah, al, woh, wol, b_out, out,
                                            B_ * T_, D_, D_, 1);
    }
}

// round 6
// speedup vs baseline: 2.3982x; 1.2450x over previous
#include <cuda_runtime.h>
#include <cuda_bf16.h>
#include <cstdint>

#define B_   2
#define T_   4096
#define D_   768
#define H_   12
#define HD_  64
#define SCALE_ 0.125f

#define QT 128
#define KT 64

// ---------------- scratch ----------------
__device__ __nv_bfloat16 g_qh[(size_t)B_ * H_ * T_ * HD_];   // [B,H,T,hd]
__device__ __nv_bfloat16 g_ql[(size_t)B_ * H_ * T_ * HD_];
__device__ __nv_bfloat16 g_kh[(size_t)B_ * H_ * T_ * HD_];
__device__ __nv_bfloat16 g_kl[(size_t)B_ * H_ * T_ * HD_];
__device__ __nv_bfloat16 g_vh[(size_t)B_ * H_ * T_ * HD_];   // TRANSPOSED: [B,H,hd,T]
__device__ __nv_bfloat16 g_vl[(size_t)B_ * H_ * T_ * HD_];
__device__ __nv_bfloat16 g_xh[(size_t)B_ * T_ * D_];
__device__ __nv_bfloat16 g_xl[(size_t)B_ * T_ * D_];
__device__ __nv_bfloat16 g_ah[(size_t)B_ * T_ * D_];
__device__ __nv_bfloat16 g_al[(size_t)B_ * T_ * D_];
__device__ __nv_bfloat16 g_wqh[(size_t)3 * D_ * D_];
__device__ __nv_bfloat16 g_wql[(size_t)3 * D_ * D_];
__device__ __nv_bfloat16 g_woh[(size_t)D_ * D_];
__device__ __nv_bfloat16 g_wol[(size_t)D_ * D_];

// ======================= helpers ========================
__device__ __forceinline__ uint32_t smem_u32(const void* p) {
    uint32_t a;
    asm("{ .reg .u64 t; cvta.to.shared.u64 t, %1; cvt.u32.u64 %0, t; }"
        : "=r"(a) : "l"(p));
    return a;
}

__device__ __forceinline__ void cp16(uint32_t s, const void* g) {
    asm volatile("cp.async.cg.shared.global [%0], [%1], 16;" :: "r"(s), "l"(g));
}
#define CP_COMMIT() asm volatile("cp.async.commit_group;" ::: "memory")
#define CP_WAIT1()  asm volatile("cp.async.wait_group 1;" ::: "memory")
#define CP_WAIT0()  asm volatile("cp.async.wait_group 0;" ::: "memory")

__device__ __forceinline__ void mma16816(float* c, const uint32_t* a, const uint32_t* b) {
    asm("mma.sync.aligned.m16n8k16.row.col.f32.bf16.bf16.f32 "
        "{%0,%1,%2,%3}, {%4,%5,%6,%7}, {%8,%9}, {%0,%1,%2,%3};"
        : "+f"(c[0]), "+f"(c[1]), "+f"(c[2]), "+f"(c[3])
        : "r"(a[0]), "r"(a[1]), "r"(a[2]), "r"(a[3]), "r"(b[0]), "r"(b[1]));
}

__device__ __forceinline__ uint32_t pack_bf(__nv_bfloat16 a, __nv_bfloat16 b) {
    __nv_bfloat162 t(a, b);
    return *reinterpret_cast<uint32_t*>(&t);
}

__device__ __forceinline__ void split2(float v0, float v1, uint32_t& hi, uint32_t& lo) {
    __nv_bfloat16 h0 = __float2bfloat16_rn(v0);
    __nv_bfloat16 h1 = __float2bfloat16_rn(v1);
    float r0 = v0 - __bfloat162float(h0);
    float r1 = v1 - __bfloat162float(h1);
    hi = pack_bf(h0, h1);
    lo = pack_bf(__float2bfloat16_rn(r0), __float2bfloat16_rn(r1));
}

// ======================================================================
// conversions
// ======================================================================
__global__ void conv_split(const float* __restrict__ in,
                           __nv_bfloat16* __restrict__ oh,
                           __nv_bfloat16* __restrict__ ol, int n)
{
    int i = blockIdx.x * blockDim.x + threadIdx.x;
    if (i >= n) return;
    float v = in[i];
    __nv_bfloat16 h = __float2bfloat16_rn(v);
    float r = v - __bfloat162float(h);
    oh[i] = h;
    ol[i] = __float2bfloat16_rn(r);
}

__global__ void conv_split_tr(const float* __restrict__ in,
                              __nv_bfloat16* __restrict__ oh,
                              __nv_bfloat16* __restrict__ ol, int K, int N)
{
    int i = blockIdx.x * blockDim.x + threadIdx.x;
    if (i >= K * N) return;
    int k = i / N, n = i % N;
    float v = in[i];
    __nv_bfloat16 h = __float2bfloat16_rn(v);
    float r = v - __bfloat162float(h);
    oh[(size_t)n * K + k] = h;
    ol[(size_t)n * K + k] = __float2bfloat16_rn(r);
}

// ======================================================================
// HMMA GEMM, bf16 split. 512 threads, 16 warps 4(M)x4(N), warp tile 32x32.
// mode 0: scatter q/k (row-major) and V TRANSPOSED; mode 1: fp32 Cout.
// ======================================================================
#define LDK 72
#define TILE_B (128 * LDK * 2)
#define TOFF(buf, t) (((buf) * 4 + (t)) * TILE_B)
#define SMEM_GT (2 * 4 * TILE_B)

__global__ void __launch_bounds__(512, 1) gemm_tc_mma(
    const __nv_bfloat16* __restrict__ Ah, const __nv_bfloat16* __restrict__ Al,
    const __nv_bfloat16* __restrict__ Bh, const __nv_bfloat16* __restrict__ Bl,
    const float* __restrict__ bias, float* __restrict__ Cout,
    int M, int N, int K, int mode)
{
    extern __shared__ char smc[];
    const uint32_t sbase = smem_u32(smc);
    const int tid  = threadIdx.x;
    const int lane = tid & 31;
    const int wid  = tid >> 5;
    const int wm   = wid & 3;        // 0..3
    const int wn   = wid >> 2;       // 0..3
    const int bm = blockIdx.y * 128;
    const int bn = blockIdx.x * 128;

    const char* gA[2] = { (const char*)(Ah + (size_t)bm * K),
                          (const char*)(Al + (size_t)bm * K) };
    const char* gB[2] = { (const char*)(Bh + (size_t)bn * K),
                          (const char*)(Bl + (size_t)bn * K) };

    const int nk = K / 64;

    auto issue_chunk = [&](int k0, int buf) {
#pragma unroll
        for (int t = 0; t < 4; t++) {
            const char* src = (t < 2) ? gA[t] : gB[t - 2];
#pragma unroll
            for (int j = 0; j < 2; j++) {
                const int idx = tid * 2 + j;       // 0..1023
                const int row = idx >> 3;
                const int c16 = idx & 7;
                cp16(sbase + TOFF(buf, t) + row * (LDK * 2) + c16 * 16,
                     src + (size_t)row * (K * 2) + k0 * 2 + c16 * 16);
            }
        }
    };

    issue_chunk(0, 0); CP_COMMIT();
    if (nk > 1) { issue_chunk(64, 1); }
    CP_COMMIT();

    float acc[2][4][4];
#pragma unroll
    for (int i = 0; i < 2; i++)
#pragma unroll
        for (int j = 0; j < 4; j++)
#pragma unroll
            for (int q = 0; q < 4; q++) acc[i][j][q] = 0.f;

    const int lr = lane >> 2;
    const int lc = (lane & 3) * 2;

    for (int it = 0; it < nk; ++it) {
        const int buf = it & 1;
        CP_WAIT1();
        __syncthreads();

        const char* sA[2] = { smc + TOFF(buf, 0), smc + TOFF(buf, 1) };
        const char* sB[2] = { smc + TOFF(buf, 2), smc + TOFF(buf, 3) };

#pragma unroll
        for (int kk = 0; kk < 4; kk++) {
            const int kb = kk * 32 + lc * 2;
            uint32_t af[2][2][4];
#pragma unroll
            for (int v = 0; v < 2; v++)
#pragma unroll
                for (int i = 0; i < 2; i++) {
                    const int r0 = (wm * 32 + i * 16 + lr) * (LDK * 2);
                    af[v][i][0] = *(const uint32_t*)(sA[v] + r0 + kb);
                    af[v][i][1] = *(const uint32_t*)(sA[v] + r0 + 8 * (LDK * 2) + kb);
                    af[v][i][2] = *(const uint32_t*)(sA[v] + r0 + kb + 16);
                    af[v][i][3] = *(const uint32_t*)(sA[v] + r0 + 8 * (LDK * 2) + kb + 16);
                }
            uint32_t bf[2][4][2];
#pragma unroll
            for (int v = 0; v < 2; v++)
#pragma unroll
                for (int j = 0; j < 4; j++) {
                    const int n0 = (wn * 32 + j * 8 + lr) * (LDK * 2);
                    bf[v][j][0] = *(const uint32_t*)(sB[v] + n0 + kb);
                    bf[v][j][1] = *(const uint32_t*)(sB[v] + n0 + kb + 16);
                }
#pragma unroll
            for (int i = 0; i < 2; i++)
#pragma unroll
                for (int j = 0; j < 4; j++)
                    mma16816(acc[i][j], af[0][i], bf[0][j]);
#pragma unroll
            for (int i = 0; i < 2; i++)
#pragma unroll
                for (int j = 0; j < 4; j++)
                    mma16816(acc[i][j], af[0][i], bf[1][j]);
#pragma unroll
            for (int i = 0; i < 2; i++)
#pragma unroll
                for (int j = 0; j < 4; j++)
                    mma16816(acc[i][j], af[1][i], bf[0][j]);
        }
        __syncthreads();
        if (it + 2 < nk) { issue_chunk((it + 2) * 64, buf); }
        CP_COMMIT();
    }

    // -------- epilogue --------
#pragma unroll
    for (int i = 0; i < 2; i++) {
        const int row0 = bm + wm * 32 + i * 16 + lr;
#pragma unroll
        for (int j = 0; j < 4; j++) {
            const int col = bn + wn * 32 + j * 8 + lc;
            const float b0 = bias[col], b1 = bias[col + 1];
            const float v00 = acc[i][j][0] + b0, v01 = acc[i][j][1] + b1;
            const float v10 = acc[i][j][2] + b0, v11 = acc[i][j][3] + b1;
            if (mode == 1) {
                *(float2*)&Cout[(size_t)row0 * N + col]       = make_float2(v00, v01);
                *(float2*)&Cout[(size_t)(row0 + 8) * N + col] = make_float2(v10, v11);
            } else {
                const int sel = col / D_;
                const int rem = col % D_;
                const int h   = rem / HD_;
                const int d0  = rem % HD_;
                const int bb0 = row0 >> 12, t0 = row0 & (T_ - 1);
                const int bb1 = (row0 + 8) >> 12, t1 = (row0 + 8) & (T_ - 1);
                if (sel == 2) {
                    // V transposed: [B,H,hd,T]
                    const size_t hb0 = (size_t)(bb0 * H_ + h) * HD_;
                    const size_t hb1 = (size_t)(bb1 * H_ + h) * HD_;
                    __nv_bfloat16 h00 = __float2bfloat16_rn(v00);
                    __nv_bfloat16 h01 = __float2bfloat16_rn(v01);
                    __nv_bfloat16 h10 = __float2bfloat16_rn(v10);
                    __nv_bfloat16 h11 = __float2bfloat16_rn(v11);
                    g_vh[(hb0 + d0)     * T_ + t0] = h00;
                    g_vh[(hb0 + d0 + 1) * T_ + t0] = h01;
                    g_vh[(hb1 + d0)     * T_ + t1] = h10;
                    g_vh[(hb1 + d0 + 1) * T_ + t1] = h11;
                    g_vl[(hb0 + d0)     * T_ + t0] = __float2bfloat16_rn(v00 - __bfloat162float(h00));
                    g_vl[(hb0 + d0 + 1) * T_ + t0] = __float2bfloat16_rn(v01 - __bfloat162float(h01));
                    g_vl[(hb1 + d0)     * T_ + t1] = __float2bfloat16_rn(v10 - __bfloat162float(h10));
                    g_vl[(hb1 + d0 + 1) * T_ + t1] = __float2bfloat16_rn(v11 - __bfloat162float(h11));
                } else {
                    __nv_bfloat16* dh = (sel == 0) ? g_qh : g_kh;
                    __nv_bfloat16* dl = (sel == 0) ? g_ql : g_kl;
                    uint32_t hi, lo;
                    split2(v00, v01, hi, lo);
                    size_t off = ((size_t)(bb0 * H_ + h) * T_ + t0) * HD_ + d0;
                    *(uint32_t*)&dh[off] = hi; *(uint32_t*)&dl[off] = lo;
                    split2(v10, v11, hi, lo);
                    off = ((size_t)(bb1 * H_ + h) * T_ + t1) * HD_ + d0;
                    *(uint32_t*)&dh[off] = hi; *(uint32_t*)&dl[off] = lo;
                }
            }
        }
    }
    CP_WAIT0();
}

// ======================================================================
// Causal flash attention on HMMA, bf16 split. V arrives pre-transposed.
// ======================================================================
#define AP  72
#define APB (AP * 2)
#define SMEM_AT (128 * APB * 2 + 64 * APB * 4)

__global__ void __launch_bounds__(256, 1) attn_mma()
{
    extern __shared__ char sm[];
    char* sQh = sm;
    char* sQl = sm + 128 * APB;
    char* sKh = sQl + 128 * APB;
    char* sKl = sKh + 64 * APB;
    char* sVh = sKl + 64 * APB;
    char* sVl = sVh + 64 * APB;

    const int tid = threadIdx.x, lane = tid & 31, wid = tid >> 5;
    const int lr = lane >> 2, lq = lane & 3;
    const int qi = (int)gridDim.x - 1 - (int)blockIdx.x;
    const int h = blockIdx.y, b = blockIdx.z;
    const int qbase = qi * QT;

    const size_t bh = (size_t)(b * H_ + h) * T_;
    const char* qh = (const char*)(g_qh + (bh + qbase) * HD_);
    const char* ql = (const char*)(g_ql + (bh + qbase) * HD_);
    const char* kh = (const char*)(g_kh + bh * HD_);
    const char* kl = (const char*)(g_kl + bh * HD_);
    const char* vh = (const char*)(g_vh + bh * HD_);   // [hd][T] rows
    const char* vl = (const char*)(g_vl + bh * HD_);

#pragma unroll
    for (int p = 0; p < 4; p++) {
        const int idx = p * 256 + tid;
        const int row = idx >> 3, c16 = idx & 7;
        *(uint4*)(sQh + row * APB + c16 * 16) =
            *(const uint4*)(qh + (size_t)row * 128 + c16 * 16);
        *(uint4*)(sQl + row * APB + c16 * 16) =
            *(const uint4*)(ql + (size_t)row * 128 + c16 * 16);
    }

    float m[2] = {-1e30f, -1e30f}, l[2] = {0.f, 0.f};
    float o[8][4];
#pragma unroll
    for (int j = 0; j < 8; j++)
#pragma unroll
        for (int q = 0; q < 4; q++) o[j][q] = 0.f;

    const int nkt = qbase / KT + 2;
    const int rowmaxw = qbase + wid * 16 + 15;

    for (int kt = 0; kt < nkt; kt++) {
        const int kb = kt * KT;
        __syncthreads();
        // stage K [key][hd] and V^T [hd][key] — both 64 rows of 128 bytes
#pragma unroll
        for (int p = 0; p < 2; p++) {
            const int idx = p * 256 + tid;
            const int row = idx >> 3, c16 = idx & 7;
            *(uint4*)(sKh + row * APB + c16 * 16) =
                *(const uint4*)(kh + (size_t)(kb + row) * 128 + c16 * 16);
            *(uint4*)(sKl + row * APB + c16 * 16) =
                *(const uint4*)(kl + (size_t)(kb + row) * 128 + c16 * 16);
            *(uint4*)(sVh + row * APB + c16 * 16) =
                *(const uint4*)(vh + (size_t)row * (T_ * 2) + kb * 2 + c16 * 16);
            *(uint4*)(sVl + row * APB + c16 * 16) =
                *(const uint4*)(vl + (size_t)row * (T_ * 2) + kb * 2 + c16 * 16);
        }
        __syncthreads();

        if (kb > rowmaxw) continue;

        // ---- S = Q K^T ----
        float s[8][4];
#pragma unroll
        for (int j = 0; j < 8; j++)
#pragma unroll
            for (int q = 0; q < 4; q++) s[j][q] = 0.f;

        const int r0 = (wid * 16 + lr) * APB;
#pragma unroll
        for (int kk = 0; kk < 4; kk++) {
            const int kbo = kk * 32 + lq * 4;
            uint32_t ah[4], al[4];
            ah[0] = *(const uint32_t*)(sQh + r0 + kbo);
            ah[1] = *(const uint32_t*)(sQh + r0 + 8 * APB + kbo);
            ah[2] = *(const uint32_t*)(sQh + r0 + kbo + 16);
            ah[3] = *(const uint32_t*)(sQh + r0 + 8 * APB + kbo + 16);
            al[0] = *(const uint32_t*)(sQl + r0 + kbo);
            al[1] = *(const uint32_t*)(sQl + r0 + 8 * APB + kbo);
            al[2] = *(const uint32_t*)(sQl + r0 + kbo + 16);
            al[3] = *(const uint32_t*)(sQl + r0 + 8 * APB + kbo + 16);
            uint32_t bh2[8][2], bl2[8][2];
#pragma unroll
            for (int j = 0; j < 8; j++) {
                const int n0 = (j * 8 + lr) * APB;
                bh2[j][0] = *(const uint32_t*)(sKh + n0 + kbo);
                bh2[j][1] = *(const uint32_t*)(sKh + n0 + kbo + 16);
                bl2[j][0] = *(const uint32_t*)(sKl + n0 + kbo);
                bl2[j][1] = *(const uint32_t*)(sKl + n0 + kbo + 16);
            }
#pragma unroll
            for (int j = 0; j < 8; j++) mma16816(s[j], ah, bh2[j]);
#pragma unroll
            for (int j = 0; j < 8; j++) mma16816(s[j], ah, bl2[j]);
#pragma unroll
            for (int j = 0; j < 8; j++) mma16816(s[j], al, bh2[j]);
        }

        // ---- scale + causal mask ----
        const bool needmask = (kb + 63) > (qbase + wid * 16);
        if (needmask) {
            const int row_a = qbase + wid * 16 + lr;
#pragma unroll
            for (int j = 0; j < 8; j++) {
                const int col0 = kb + j * 8 + lq * 2;
                s[j][0] = (col0     <= row_a)     ? s[j][0] * SCALE_ : -1e30f;
                s[j][1] = (col0 + 1 <= row_a)     ? s[j][1] * SCALE_ : -1e30f;
                s[j][2] = (col0     <= row_a + 8) ? s[j][2] * SCALE_ : -1e30f;
                s[j][3] = (col0 + 1 <= row_a + 8) ? s[j][3] * SCALE_ : -1e30f;
            }
        } else {
#pragma unroll
            for (int j = 0; j < 8; j++)
#pragma unroll
                for (int q = 0; q < 4; q++) s[j][q] *= SCALE_;
        }

        // ---- online softmax ----
#pragma unroll
        for (int r = 0; r < 2; r++) {
            float mx = -1e30f;
#pragma unroll
            for (int j = 0; j < 8; j++)
                mx = fmaxf(mx, fmaxf(s[j][2 * r], s[j][2 * r + 1]));
            mx = fmaxf(mx, __shfl_xor_sync(0xffffffffu, mx, 1));
            mx = fmaxf(mx, __shfl_xor_sync(0xffffffffu, mx, 2));
            const float mnew = fmaxf(m[r], mx);
            const float corr = __expf(m[r] - mnew);
            float sum = 0.f;
#pragma unroll
            for (int j = 0; j < 8; j++) {
                const float p0 = __expf(s[j][2 * r]     - mnew);
                const float p1 = __expf(s[j][2 * r + 1] - mnew);
                s[j][2 * r] = p0; s[j][2 * r + 1] = p1;
                sum += p0 + p1;
            }
            sum += __shfl_xor_sync(0xffffffffu, sum, 1);
            sum += __shfl_xor_sync(0xffffffffu, sum, 2);
            l[r] = l[r] * corr + sum;
            m[r] = mnew;
#pragma unroll
            for (int j = 0; j < 8; j++) {
                o[j][2 * r] *= corr; o[j][2 * r + 1] *= corr;
            }
        }

        // ---- P fragments (split) ----
        uint32_t ph0[8], ph1[8], pl0[8], pl1[8];
#pragma unroll
        for (int j = 0; j < 8; j++) {
            split2(s[j][0], s[j][1], ph0[j], pl0[j]);
            split2(s[j][2], s[j][3], ph1[j], pl1[j]);
        }

        // ---- O += P V ----
#pragma unroll
        for (int kk = 0; kk < 4; kk++) {
            uint32_t a_h[4] = { ph0[2 * kk], ph1[2 * kk], ph0[2 * kk + 1], ph1[2 * kk + 1] };
            uint32_t a_l[4] = { pl0[2 * kk], pl1[2 * kk], pl0[2 * kk + 1], pl1[2 * kk + 1] };
            const int kbo = kk * 32 + lq * 4;
            uint32_t vh2[8][2], vl2[8][2];
#pragma unroll
            for (int jn = 0; jn < 8; jn++) {
                const int n0 = (jn * 8 + lr) * APB;
                vh2[jn][0] = *(const uint32_t*)(sVh + n0 + kbo);
                vh2[jn][1] = *(const uint32_t*)(sVh + n0 + kbo + 16);
                vl2[jn][0] = *(const uint32_t*)(sVl + n0 + kbo);
                vl2[jn][1] = *(const uint32_t*)(sVl + n0 + kbo + 16);
            }
#pragma unroll
            for (int jn = 0; jn < 8; jn++) mma16816(o[jn], a_h, vh2[jn]);
#pragma unroll
            for (int jn = 0; jn < 8; jn++) mma16816(o[jn], a_h, vl2[jn]);
#pragma unroll
            for (int jn = 0; jn < 8; jn++) mma16816(o[jn], a_l, vh2[jn]);
        }
    }

    // ---- epilogue ----
    const float inv0 = 1.f / l[0], inv1 = 1.f / l[1];
    const int t0 = qbase + wid * 16 + lr;
    const int t1 = t0 + 8;
#pragma unroll
    for (int jn = 0; jn < 8; jn++) {
        const int d = h * HD_ + jn * 8 + lq * 2;
        uint32_t hi, lo;
        split2(o[jn][0] * inv0, o[jn][1] * inv0, hi, lo);
        size_t off = (size_t)(b * T_ + t0) * D_ + d;
        *(uint32_t*)&g_ah[off] = hi; *(uint32_t*)&g_al[off] = lo;
        split2(o[jn][2] * inv1, o[jn][3] * inv1, hi, lo);
        off = (size_t)(b * T_ + t1) * D_ + d;
        *(uint32_t*)&g_ah[off] = hi; *(uint32_t*)&g_al[off] = lo;
    }
}

// ======================================================================
extern "C" void kernel_launch(void* const* d_in, const int* in_sizes, int n_in,
                              void* d_out, int out_size)
{
    const float* x      = (const float*)d_in[0];
    const float* W_qkv  = (const float*)d_in[1];
    const float* b_qkv  = (const float*)d_in[2];
    const float* W_out  = (const float*)d_in[3];
    const float* b_out  = (const float*)d_in[4];
    float* out = (float*)d_out;

    __nv_bfloat16 *xh, *xl, *ah, *al, *wqh, *wql, *woh, *wol;
    cudaGetSymbolAddress((void**)&xh,  g_xh);
    cudaGetSymbolAddress((void**)&xl,  g_xl);
    cudaGetSymbolAddress((void**)&ah,  g_ah);
    cudaGetSymbolAddress((void**)&al,  g_al);
    cudaGetSymbolAddress((void**)&wqh, g_wqh);
    cudaGetSymbolAddress((void**)&wql, g_wql);
    cudaGetSymbolAddress((void**)&woh, g_woh);
    cudaGetSymbolAddress((void**)&wol, g_wol);

    cudaFuncSetAttribute(gemm_tc_mma, cudaFuncAttributeMaxDynamicSharedMemorySize, SMEM_GT);
    cudaFuncSetAttribute(attn_mma,    cudaFuncAttributeMaxDynamicSharedMemorySize, SMEM_AT);

    const int nX = B_ * T_ * D_;

    conv_split<<<(nX + 255) / 256, 256>>>(x, xh, xl, nX);
    conv_split_tr<<<(D_ * 3 * D_ + 255) / 256, 256>>>(W_qkv, wqh, wql, D_, 3 * D_);
    conv_split_tr<<<(D_ * D_ + 255) / 256, 256>>>(W_out, woh, wol, D_, D_);

    {
        dim3 grid((3 * D_) / 128, (B_ * T_) / 128);
        gemm_tc_mma<<<grid, 512, SMEM_GT>>>(xh, xl, wqh, wql, b_qkv, nullptr,
                                            B_ * T_, 3 * D_, D_, 0);
    }
    {
        dim3 grid(T_ / QT, H_, B_);
        attn_mma<<<grid, 256, SMEM_AT>>>();
    }
    {
        dim3 grid(D_ / 128, (B_ * T_) / 128);
        gemm_tc_mma<<<grid, 512, SMEM_GT>>>(ah, al, woh, wol, b_out, out,
                                            B_ * T_, D_, D_, 1);
    }
}

// round 7
// speedup vs baseline: 2.4212x; 1.0096x over previous
#include <cuda_runtime.h>
#include <cuda_bf16.h>
#include <cstdint>

#define B_   2
#define T_   4096
#define D_   768
#define H_   12
#define HD_  64
#define SCALE_ 0.125f

#define QT 128
#define KT 64

// ---------------- scratch ----------------
__device__ __nv_bfloat16 g_qh[(size_t)B_ * H_ * T_ * HD_];   // [B,H,T,hd]
__device__ __nv_bfloat16 g_ql[(size_t)B_ * H_ * T_ * HD_];
__device__ __nv_bfloat16 g_kh[(size_t)B_ * H_ * T_ * HD_];
__device__ __nv_bfloat16 g_kl[(size_t)B_ * H_ * T_ * HD_];
__device__ __nv_bfloat16 g_vh[(size_t)B_ * H_ * T_ * HD_];   // TRANSPOSED: [B,H,hd,T]
__device__ __nv_bfloat16 g_vl[(size_t)B_ * H_ * T_ * HD_];
__device__ __nv_bfloat16 g_xh[(size_t)B_ * T_ * D_];
__device__ __nv_bfloat16 g_xl[(size_t)B_ * T_ * D_];
__device__ __nv_bfloat16 g_ah[(size_t)B_ * T_ * D_];
__device__ __nv_bfloat16 g_al[(size_t)B_ * T_ * D_];
__device__ __nv_bfloat16 g_wqh[(size_t)3 * D_ * D_];
__device__ __nv_bfloat16 g_wql[(size_t)3 * D_ * D_];
__device__ __nv_bfloat16 g_woh[(size_t)D_ * D_];
__device__ __nv_bfloat16 g_wol[(size_t)D_ * D_];

// ======================= helpers ========================
__device__ __forceinline__ uint32_t smem_u32(const void* p) {
    uint32_t a;
    asm("{ .reg .u64 t; cvta.to.shared.u64 t, %1; cvt.u32.u64 %0, t; }"
        : "=r"(a) : "l"(p));
    return a;
}

__device__ __forceinline__ void cp16(uint32_t s, const void* g) {
    asm volatile("cp.async.cg.shared.global [%0], [%1], 16;" :: "r"(s), "l"(g));
}
#define CP_COMMIT() asm volatile("cp.async.commit_group;" ::: "memory")
#define CP_WAIT1()  asm volatile("cp.async.wait_group 1;" ::: "memory")
#define CP_WAIT0()  asm volatile("cp.async.wait_group 0;" ::: "memory")

__device__ __forceinline__ void mma16816(float* c, const uint32_t* a, const uint32_t* b) {
    asm("mma.sync.aligned.m16n8k16.row.col.f32.bf16.bf16.f32 "
        "{%0,%1,%2,%3}, {%4,%5,%6,%7}, {%8,%9}, {%0,%1,%2,%3};"
        : "+f"(c[0]), "+f"(c[1]), "+f"(c[2]), "+f"(c[3])
        : "r"(a[0]), "r"(a[1]), "r"(a[2]), "r"(a[3]), "r"(b[0]), "r"(b[1]));
}

__device__ __forceinline__ uint32_t pack_bf(__nv_bfloat16 a, __nv_bfloat16 b) {
    __nv_bfloat162 t(a, b);
    return *reinterpret_cast<uint32_t*>(&t);
}

__device__ __forceinline__ void split2(float v0, float v1, uint32_t& hi, uint32_t& lo) {
    __nv_bfloat16 h0 = __float2bfloat16_rn(v0);
    __nv_bfloat16 h1 = __float2bfloat16_rn(v1);
    float r0 = v0 - __bfloat162float(h0);
    float r1 = v1 - __bfloat162float(h1);
    hi = pack_bf(h0, h1);
    lo = pack_bf(__float2bfloat16_rn(r0), __float2bfloat16_rn(r1));
}

// ======================================================================
// conversions
// ======================================================================
__global__ void conv_split(const float* __restrict__ in,
                           __nv_bfloat16* __restrict__ oh,
                           __nv_bfloat16* __restrict__ ol, int n)
{
    int i = blockIdx.x * blockDim.x + threadIdx.x;
    if (i >= n) return;
    float v = in[i];
    __nv_bfloat16 h = __float2bfloat16_rn(v);
    float r = v - __bfloat162float(h);
    oh[i] = h;
    ol[i] = __float2bfloat16_rn(r);
}

__global__ void conv_split_tr(const float* __restrict__ in,
                              __nv_bfloat16* __restrict__ oh,
                              __nv_bfloat16* __restrict__ ol, int K, int N)
{
    int i = blockIdx.x * blockDim.x + threadIdx.x;
    if (i >= K * N) return;
    int k = i / N, n = i % N;
    float v = in[i];
    __nv_bfloat16 h = __float2bfloat16_rn(v);
    float r = v - __bfloat162float(h);
    oh[(size_t)n * K + k] = h;
    ol[(size_t)n * K + k] = __float2bfloat16_rn(r);
}

// ======================================================================
// HMMA GEMM, bf16 split, 512 threads (16 warps 4x4, warp tile 32x32),
// register-level fragment double buffering (LDS overlaps MMA).
// ======================================================================
#define LDK 72
#define TILE_B (128 * LDK * 2)
#define TOFF(buf, t) (((buf) * 4 + (t)) * TILE_B)
#define SMEM_GT (2 * 4 * TILE_B)

__global__ void __launch_bounds__(512, 1) gemm_tc_mma(
    const __nv_bfloat16* __restrict__ Ah, const __nv_bfloat16* __restrict__ Al,
    const __nv_bfloat16* __restrict__ Bh, const __nv_bfloat16* __restrict__ Bl,
    const float* __restrict__ bias, float* __restrict__ Cout,
    int M, int N, int K, int mode)
{
    extern __shared__ char smc[];
    const uint32_t sbase = smem_u32(smc);
    const int tid  = threadIdx.x;
    const int lane = tid & 31;
    const int wid  = tid >> 5;
    const int wm   = wid & 3;
    const int wn   = wid >> 2;
    const int bm = blockIdx.y * 128;
    const int bn = blockIdx.x * 128;

    const char* gA[2] = { (const char*)(Ah + (size_t)bm * K),
                          (const char*)(Al + (size_t)bm * K) };
    const char* gB[2] = { (const char*)(Bh + (size_t)bn * K),
                          (const char*)(Bl + (size_t)bn * K) };

    const int nk = K / 64;

    auto issue_chunk = [&](int k0, int buf) {
#pragma unroll
        for (int t = 0; t < 4; t++) {
            const char* src = (t < 2) ? gA[t] : gB[t - 2];
#pragma unroll
            for (int j = 0; j < 2; j++) {
                const int idx = tid * 2 + j;
                const int row = idx >> 3;
                const int c16 = idx & 7;
                cp16(sbase + TOFF(buf, t) + row * (LDK * 2) + c16 * 16,
                     src + (size_t)row * (K * 2) + k0 * 2 + c16 * 16);
            }
        }
    };

    issue_chunk(0, 0); CP_COMMIT();
    if (nk > 1) { issue_chunk(64, 1); }
    CP_COMMIT();

    float acc[2][4][4];
#pragma unroll
    for (int i = 0; i < 2; i++)
#pragma unroll
        for (int j = 0; j < 4; j++)
#pragma unroll
            for (int q = 0; q < 4; q++) acc[i][j][q] = 0.f;

    const int lr = lane >> 2;
    const int lc = (lane & 3) * 2;

    // double-buffered fragment registers
    uint32_t af[2][2][2][4];   // [pb][v][i][4]
    uint32_t bf[2][2][4][2];   // [pb][v][j][2]

    for (int it = 0; it < nk; ++it) {
        const int buf = it & 1;
        CP_WAIT1();
        __syncthreads();

        const char* sA[2] = { smc + TOFF(buf, 0), smc + TOFF(buf, 1) };
        const char* sB[2] = { smc + TOFF(buf, 2), smc + TOFF(buf, 3) };

        auto loadf = [&](int kk, int pb) {
            const int kb = kk * 32 + lc * 2;
#pragma unroll
            for (int v = 0; v < 2; v++) {
#pragma unroll
                for (int i = 0; i < 2; i++) {
                    const int r0 = (wm * 32 + i * 16 + lr) * (LDK * 2);
                    af[pb][v][i][0] = *(const uint32_t*)(sA[v] + r0 + kb);
                    af[pb][v][i][1] = *(const uint32_t*)(sA[v] + r0 + 8 * (LDK * 2) + kb);
                    af[pb][v][i][2] = *(const uint32_t*)(sA[v] + r0 + kb + 16);
                    af[pb][v][i][3] = *(const uint32_t*)(sA[v] + r0 + 8 * (LDK * 2) + kb + 16);
                }
#pragma unroll
                for (int j = 0; j < 4; j++) {
                    const int n0 = (wn * 32 + j * 8 + lr) * (LDK * 2);
                    bf[pb][v][j][0] = *(const uint32_t*)(sB[v] + n0 + kb);
                    bf[pb][v][j][1] = *(const uint32_t*)(sB[v] + n0 + kb + 16);
                }
            }
        };

        loadf(0, 0);
#pragma unroll
        for (int kk = 0; kk < 4; kk++) {
            const int pb = kk & 1;
            if (kk < 3) loadf(kk + 1, pb ^ 1);
#pragma unroll
            for (int i = 0; i < 2; i++)
#pragma unroll
                for (int j = 0; j < 4; j++)
                    mma16816(acc[i][j], af[pb][0][i], bf[pb][0][j]);
#pragma unroll
            for (int i = 0; i < 2; i++)
#pragma unroll
                for (int j = 0; j < 4; j++)
                    mma16816(acc[i][j], af[pb][0][i], bf[pb][1][j]);
#pragma unroll
            for (int i = 0; i < 2; i++)
#pragma unroll
                for (int j = 0; j < 4; j++)
                    mma16816(acc[i][j], af[pb][1][i], bf[pb][0][j]);
        }
        __syncthreads();
        if (it + 2 < nk) { issue_chunk((it + 2) * 64, buf); }
        CP_COMMIT();
    }

    // -------- epilogue --------
#pragma unroll
    for (int i = 0; i < 2; i++) {
        const int row0 = bm + wm * 32 + i * 16 + lr;
#pragma unroll
        for (int j = 0; j < 4; j++) {
            const int col = bn + wn * 32 + j * 8 + lc;
            const float b0 = bias[col], b1 = bias[col + 1];
            const float v00 = acc[i][j][0] + b0, v01 = acc[i][j][1] + b1;
            const float v10 = acc[i][j][2] + b0, v11 = acc[i][j][3] + b1;
            if (mode == 1) {
                *(float2*)&Cout[(size_t)row0 * N + col]       = make_float2(v00, v01);
                *(float2*)&Cout[(size_t)(row0 + 8) * N + col] = make_float2(v10, v11);
            } else {
                const int sel = col / D_;
                const int rem = col % D_;
                const int h   = rem / HD_;
                const int d0  = rem % HD_;
                const int bb0 = row0 >> 12, t0 = row0 & (T_ - 1);
                const int bb1 = (row0 + 8) >> 12, t1 = (row0 + 8) & (T_ - 1);
                if (sel == 2) {
                    const size_t hb0 = (size_t)(bb0 * H_ + h) * HD_;
                    const size_t hb1 = (size_t)(bb1 * H_ + h) * HD_;
                    __nv_bfloat16 h00 = __float2bfloat16_rn(v00);
                    __nv_bfloat16 h01 = __float2bfloat16_rn(v01);
                    __nv_bfloat16 h10 = __float2bfloat16_rn(v10);
                    __nv_bfloat16 h11 = __float2bfloat16_rn(v11);
                    g_vh[(hb0 + d0)     * T_ + t0] = h00;
                    g_vh[(hb0 + d0 + 1) * T_ + t0] = h01;
                    g_vh[(hb1 + d0)     * T_ + t1] = h10;
                    g_vh[(hb1 + d0 + 1) * T_ + t1] = h11;
                    g_vl[(hb0 + d0)     * T_ + t0] = __float2bfloat16_rn(v00 - __bfloat162float(h00));
                    g_vl[(hb0 + d0 + 1) * T_ + t0] = __float2bfloat16_rn(v01 - __bfloat162float(h01));
                    g_vl[(hb1 + d0)     * T_ + t1] = __float2bfloat16_rn(v10 - __bfloat162float(h10));
                    g_vl[(hb1 + d0 + 1) * T_ + t1] = __float2bfloat16_rn(v11 - __bfloat162float(h11));
                } else {
                    __nv_bfloat16* dh = (sel == 0) ? g_qh : g_kh;
                    __nv_bfloat16* dl = (sel == 0) ? g_ql : g_kl;
                    uint32_t hi, lo;
                    split2(v00, v01, hi, lo);
                    size_t off = ((size_t)(bb0 * H_ + h) * T_ + t0) * HD_ + d0;
                    *(uint32_t*)&dh[off] = hi; *(uint32_t*)&dl[off] = lo;
                    split2(v10, v11, hi, lo);
                    off = ((size_t)(bb1 * H_ + h) * T_ + t1) * HD_ + d0;
                    *(uint32_t*)&dh[off] = hi; *(uint32_t*)&dl[off] = lo;
                }
            }
        }
    }
    CP_WAIT0();
}

// ======================================================================
// Causal flash attention on HMMA: Q fragments hoisted to registers,
// K / V fragments double-buffered (LDS overlaps MMA).
// ======================================================================
#define AP  72
#define APB (AP * 2)
#define SMEM_AT (128 * APB * 2 + 64 * APB * 4)

__global__ void __launch_bounds__(256, 1) attn_mma()
{
    extern __shared__ char sm[];
    char* sQh = sm;
    char* sQl = sm + 128 * APB;
    char* sKh = sQl + 128 * APB;
    char* sKl = sKh + 64 * APB;
    char* sVh = sKl + 64 * APB;
    char* sVl = sVh + 64 * APB;

    const int tid = threadIdx.x, lane = tid & 31, wid = tid >> 5;
    const int lr = lane >> 2, lq = lane & 3;
    const int qi = (int)gridDim.x - 1 - (int)blockIdx.x;
    const int h = blockIdx.y, b = blockIdx.z;
    const int qbase = qi * QT;

    const size_t bh = (size_t)(b * H_ + h) * T_;
    const char* qh = (const char*)(g_qh + (bh + qbase) * HD_);
    const char* ql = (const char*)(g_ql + (bh + qbase) * HD_);
    const char* kh = (const char*)(g_kh + bh * HD_);
    const char* kl = (const char*)(g_kl + bh * HD_);
    const char* vh = (const char*)(g_vh + bh * HD_);   // [hd][T]
    const char* vl = (const char*)(g_vl + bh * HD_);

#pragma unroll
    for (int p = 0; p < 4; p++) {
        const int idx = p * 256 + tid;
        const int row = idx >> 3, c16 = idx & 7;
        *(uint4*)(sQh + row * APB + c16 * 16) =
            *(const uint4*)(qh + (size_t)row * 128 + c16 * 16);
        *(uint4*)(sQl + row * APB + c16 * 16) =
            *(const uint4*)(ql + (size_t)row * 128 + c16 * 16);
    }
    __syncthreads();

    // ---- hoist Q fragments: qf[kk][v][4] ----
    uint32_t qf[4][2][4];
    {
        const int r0 = (wid * 16 + lr) * APB;
#pragma unroll
        for (int kk = 0; kk < 4; kk++) {
            const int kbo = kk * 32 + lq * 4;
            qf[kk][0][0] = *(const uint32_t*)(sQh + r0 + kbo);
            qf[kk][0][1] = *(const uint32_t*)(sQh + r0 + 8 * APB + kbo);
            qf[kk][0][2] = *(const uint32_t*)(sQh + r0 + kbo + 16);
            qf[kk][0][3] = *(const uint32_t*)(sQh + r0 + 8 * APB + kbo + 16);
            qf[kk][1][0] = *(const uint32_t*)(sQl + r0 + kbo);
            qf[kk][1][1] = *(const uint32_t*)(sQl + r0 + 8 * APB + kbo);
            qf[kk][1][2] = *(const uint32_t*)(sQl + r0 + kbo + 16);
            qf[kk][1][3] = *(const uint32_t*)(sQl + r0 + 8 * APB + kbo + 16);
        }
    }

    float m[2] = {-1e30f, -1e30f}, l[2] = {0.f, 0.f};
    float o[8][4];
#pragma unroll
    for (int j = 0; j < 8; j++)
#pragma unroll
        for (int q = 0; q < 4; q++) o[j][q] = 0.f;

    const int nkt = qbase / KT + 2;
    const int rowmaxw = qbase + wid * 16 + 15;

    // double-buffered B fragments (shared between S and PV phases)
    uint32_t bfh[2][8][2], bfl[2][8][2];

    for (int kt = 0; kt < nkt; kt++) {
        const int kb = kt * KT;
        __syncthreads();
#pragma unroll
        for (int p = 0; p < 2; p++) {
            const int idx = p * 256 + tid;
            const int row = idx >> 3, c16 = idx & 7;
            *(uint4*)(sKh + row * APB + c16 * 16) =
                *(const uint4*)(kh + (size_t)(kb + row) * 128 + c16 * 16);
            *(uint4*)(sKl + row * APB + c16 * 16) =
                *(const uint4*)(kl + (size_t)(kb + row) * 128 + c16 * 16);
            *(uint4*)(sVh + row * APB + c16 * 16) =
                *(const uint4*)(vh + (size_t)row * (T_ * 2) + kb * 2 + c16 * 16);
            *(uint4*)(sVl + row * APB + c16 * 16) =
                *(const uint4*)(vl + (size_t)row * (T_ * 2) + kb * 2 + c16 * 16);
        }
        __syncthreads();

        if (kb > rowmaxw) continue;

        // ---- S = Q K^T (pipelined) ----
        float s[8][4];
#pragma unroll
        for (int j = 0; j < 8; j++)
#pragma unroll
            for (int q = 0; q < 4; q++) s[j][q] = 0.f;

        auto loadK = [&](int kk, int pb) {
            const int kbo = kk * 32 + lq * 4;
#pragma unroll
            for (int j = 0; j < 8; j++) {
                const int n0 = (j * 8 + lr) * APB;
                bfh[pb][j][0] = *(const uint32_t*)(sKh + n0 + kbo);
                bfh[pb][j][1] = *(const uint32_t*)(sKh + n0 + kbo + 16);
                bfl[pb][j][0] = *(const uint32_t*)(sKl + n0 + kbo);
                bfl[pb][j][1] = *(const uint32_t*)(sKl + n0 + kbo + 16);
            }
        };

        loadK(0, 0);
#pragma unroll
        for (int kk = 0; kk < 4; kk++) {
            const int pb = kk & 1;
            if (kk < 3) loadK(kk + 1, pb ^ 1);
#pragma unroll
            for (int j = 0; j < 8; j++) mma16816(s[j], qf[kk][0], bfh[pb][j]);
#pragma unroll
            for (int j = 0; j < 8; j++) mma16816(s[j], qf[kk][0], bfl[pb][j]);
#pragma unroll
            for (int j = 0; j < 8; j++) mma16816(s[j], qf[kk][1], bfh[pb][j]);
        }

        // ---- scale + causal mask ----
        const bool needmask = (kb + 63) > (qbase + wid * 16);
        if (needmask) {
            const int row_a = qbase + wid * 16 + lr;
#pragma unroll
            for (int j = 0; j < 8; j++) {
                const int col0 = kb + j * 8 + lq * 2;
                s[j][0] = (col0     <= row_a)     ? s[j][0] * SCALE_ : -1e30f;
                s[j][1] = (col0 + 1 <= row_a)     ? s[j][1] * SCALE_ : -1e30f;
                s[j][2] = (col0     <= row_a + 8) ? s[j][2] * SCALE_ : -1e30f;
                s[j][3] = (col0 + 1 <= row_a + 8) ? s[j][3] * SCALE_ : -1e30f;
            }
        } else {
#pragma unroll
            for (int j = 0; j < 8; j++)
#pragma unroll
                for (int q = 0; q < 4; q++) s[j][q] *= SCALE_;
        }

        // ---- online softmax ----
#pragma unroll
        for (int r = 0; r < 2; r++) {
            float mx = -1e30f;
#pragma unroll
            for (int j = 0; j < 8; j++)
                mx = fmaxf(mx, fmaxf(s[j][2 * r], s[j][2 * r + 1]));
            mx = fmaxf(mx, __shfl_xor_sync(0xffffffffu, mx, 1));
            mx = fmaxf(mx, __shfl_xor_sync(0xffffffffu, mx, 2));
            const float mnew = fmaxf(m[r], mx);
            const float corr = __expf(m[r] - mnew);
            float sum = 0.f;
#pragma unroll
            for (int j = 0; j < 8; j++) {
                const float p0 = __expf(s[j][2 * r]     - mnew);
                const float p1 = __expf(s[j][2 * r + 1] - mnew);
                s[j][2 * r] = p0; s[j][2 * r + 1] = p1;
                sum += p0 + p1;
            }
            sum += __shfl_xor_sync(0xffffffffu, sum, 1);
            sum += __shfl_xor_sync(0xffffffffu, sum, 2);
            l[r] = l[r] * corr + sum;
            m[r] = mnew;
#pragma unroll
            for (int j = 0; j < 8; j++) {
                o[j][2 * r] *= corr; o[j][2 * r + 1] *= corr;
            }
        }

        // ---- P fragments (split) ----
        uint32_t ph0[8], ph1[8], pl0[8], pl1[8];
#pragma unroll
        for (int j = 0; j < 8; j++) {
            split2(s[j][0], s[j][1], ph0[j], pl0[j]);
            split2(s[j][2], s[j][3], ph1[j], pl1[j]);
        }

        // ---- O += P V (pipelined) ----
        auto loadV = [&](int kk, int pb) {
            const int kbo = kk * 32 + lq * 4;
#pragma unroll
            for (int jn = 0; jn < 8; jn++) {
                const int n0 = (jn * 8 + lr) * APB;
                bfh[pb][jn][0] = *(const uint32_t*)(sVh + n0 + kbo);
                bfh[pb][jn][1] = *(const uint32_t*)(sVh + n0 + kbo + 16);
                bfl[pb][jn][0] = *(const uint32_t*)(sVl + n0 + kbo);
                bfl[pb][jn][1] = *(const uint32_t*)(sVl + n0 + kbo + 16);
            }
        };

        loadV(0, 0);
#pragma unroll
        for (int kk = 0; kk < 4; kk++) {
            const int pb = kk & 1;
            if (kk < 3) loadV(kk + 1, pb ^ 1);
            uint32_t a_h[4] = { ph0[2 * kk], ph1[2 * kk], ph0[2 * kk + 1], ph1[2 * kk + 1] };
            uint32_t a_l[4] = { pl0[2 * kk], pl1[2 * kk], pl0[2 * kk + 1], pl1[2 * kk + 1] };
#pragma unroll
            for (int jn = 0; jn < 8; jn++) mma16816(o[jn], a_h, bfh[pb][jn]);
#pragma unroll
            for (int jn = 0; jn < 8; jn++) mma16816(o[jn], a_h, bfl[pb][jn]);
#pragma unroll
            for (int jn = 0; jn < 8; jn++) mma16816(o[jn], a_l, bfh[pb][jn]);
        }
    }

    // ---- epilogue ----
    const float inv0 = 1.f / l[0], inv1 = 1.f / l[1];
    const int t0 = qbase + wid * 16 + lr;
    const int t1 = t0 + 8;
#pragma unroll
    for (int jn = 0; jn < 8; jn++) {
        const int d = h * HD_ + jn * 8 + lq * 2;
        uint32_t hi, lo;
        split2(o[jn][0] * inv0, o[jn][1] * inv0, hi, lo);
        size_t off = (size_t)(b * T_ + t0) * D_ + d;
        *(uint32_t*)&g_ah[off] = hi; *(uint32_t*)&g_al[off] = lo;
        split2(o[jn][2] * inv1, o[jn][3] * inv1, hi, lo);
        off = (size_t)(b * T_ + t1) * D_ + d;
        *(uint32_t*)&g_ah[off] = hi; *(uint32_t*)&g_al[off] = lo;
    }
}

// ======================================================================
extern "C" void kernel_launch(void* const* d_in, const int* in_sizes, int n_in,
                              void* d_out, int out_size)
{
    const float* x      = (const float*)d_in[0];
    const float* W_qkv  = (const float*)d_in[1];
    const float* b_qkv  = (const float*)d_in[2];
    const float* W_out  = (const float*)d_in[3];
    const float* b_out  = (const float*)d_in[4];
    float* out = (float*)d_out;

    __nv_bfloat16 *xh, *xl, *ah, *al, *wqh, *wql, *woh, *wol;
    cudaGetSymbolAddress((void**)&xh,  g_xh);
    cudaGetSymbolAddress((void**)&xl,  g_xl);
    cudaGetSymbolAddress((void**)&ah,  g_ah);
    cudaGetSymbolAddress((void**)&al,  g_al);
    cudaGetSymbolAddress((void**)&wqh, g_wqh);
    cudaGetSymbolAddress((void**)&wql, g_wql);
    cudaGetSymbolAddress((void**)&woh, g_woh);
    cudaGetSymbolAddress((void**)&wol, g_wol);

    cudaFuncSetAttribute(gemm_tc_mma, cudaFuncAttributeMaxDynamicSharedMemorySize, SMEM_GT);
    cudaFuncSetAttribute(attn_mma,    cudaFuncAttributeMaxDynamicSharedMemorySize, SMEM_AT);

    const int nX = B_ * T_ * D_;

    conv_split<<<(nX + 255) / 256, 256>>>(x, xh, xl, nX);
    conv_split_tr<<<(D_ * 3 * D_ + 255) / 256, 256>>>(W_qkv, wqh, wql, D_, 3 * D_);
    conv_split_tr<<<(D_ * D_ + 255) / 256, 256>>>(W_out, woh, wol, D_, D_);

    {
        dim3 grid((3 * D_) / 128, (B_ * T_) / 128);
        gemm_tc_mma<<<grid, 512, SMEM_GT>>>(xh, xl, wqh, wql, b_qkv, nullptr,
                                            B_ * T_, 3 * D_, D_, 0);
    }
    {
        dim3 grid(T_ / QT, H_, B_);
        attn_mma<<<grid, 256, SMEM_AT>>>();
    }
    {
        dim3 grid(D_ / 128, (B_ * T_) / 128);
        gemm_tc_mma<<<grid, 512, SMEM_GT>>>(ah, al, woh, wol, b_out, out,
                                            B_ * T_, D_, D_, 1);
    }
}

// round 8
// speedup vs baseline: 2.5397x; 1.0489x over previous
#include <cuda_runtime.h>
#include <cuda_bf16.h>
#include <cstdint>

#define B_   2
#define T_   4096
#define D_   768
#define H_   12
#define HD_  64
#define SCALE_ 0.125f

#define QT 128
#define KT 64

// ---------------- scratch ----------------
__device__ __nv_bfloat16 g_qh[(size_t)B_ * H_ * T_ * HD_];   // [B,H,T,hd]
__device__ __nv_bfloat16 g_ql[(size_t)B_ * H_ * T_ * HD_];
__device__ __nv_bfloat16 g_kh[(size_t)B_ * H_ * T_ * HD_];
__device__ __nv_bfloat16 g_kl[(size_t)B_ * H_ * T_ * HD_];
__device__ __nv_bfloat16 g_vh[(size_t)B_ * H_ * T_ * HD_];   // TRANSPOSED: [B,H,hd,T]
__device__ __nv_bfloat16 g_vl[(size_t)B_ * H_ * T_ * HD_];
__device__ __nv_bfloat16 g_xh[(size_t)B_ * T_ * D_];
__device__ __nv_bfloat16 g_xl[(size_t)B_ * T_ * D_];
__device__ __nv_bfloat16 g_ah[(size_t)B_ * T_ * D_];
__device__ __nv_bfloat16 g_al[(size_t)B_ * T_ * D_];
__device__ __nv_bfloat16 g_wqh[(size_t)3 * D_ * D_];
__device__ __nv_bfloat16 g_wql[(size_t)3 * D_ * D_];
__device__ __nv_bfloat16 g_woh[(size_t)D_ * D_];
__device__ __nv_bfloat16 g_wol[(size_t)D_ * D_];

// ======================= helpers ========================
__device__ __forceinline__ uint32_t smem_u32(const void* p) {
    uint32_t a;
    asm("{ .reg .u64 t; cvta.to.shared.u64 t, %1; cvt.u32.u64 %0, t; }"
        : "=r"(a) : "l"(p));
    return a;
}

__device__ __forceinline__ void cp16(uint32_t s, const void* g) {
    asm volatile("cp.async.cg.shared.global [%0], [%1], 16;" :: "r"(s), "l"(g));
}
#define CP_COMMIT() asm volatile("cp.async.commit_group;" ::: "memory")
#define CP_WAIT1()  asm volatile("cp.async.wait_group 1;" ::: "memory")
#define CP_WAIT0()  asm volatile("cp.async.wait_group 0;" ::: "memory")

__device__ __forceinline__ void mma16816(float* c, const uint32_t* a, const uint32_t* b) {
    asm("mma.sync.aligned.m16n8k16.row.col.f32.bf16.bf16.f32 "
        "{%0,%1,%2,%3}, {%4,%5,%6,%7}, {%8,%9}, {%0,%1,%2,%3};"
        : "+f"(c[0]), "+f"(c[1]), "+f"(c[2]), "+f"(c[3])
        : "r"(a[0]), "r"(a[1]), "r"(a[2]), "r"(a[3]), "r"(b[0]), "r"(b[1]));
}

__device__ __forceinline__ uint32_t pack_bf(__nv_bfloat16 a, __nv_bfloat16 b) {
    __nv_bfloat162 t(a, b);
    return *reinterpret_cast<uint32_t*>(&t);
}

__device__ __forceinline__ void split2(float v0, float v1, uint32_t& hi, uint32_t& lo) {
    __nv_bfloat16 h0 = __float2bfloat16_rn(v0);
    __nv_bfloat16 h1 = __float2bfloat16_rn(v1);
    float r0 = v0 - __bfloat162float(h0);
    float r1 = v1 - __bfloat162float(h1);
    hi = pack_bf(h0, h1);
    lo = pack_bf(__float2bfloat16_rn(r0), __float2bfloat16_rn(r1));
}

// ======================================================================
// conversions
// ======================================================================
__global__ void conv_split(const float* __restrict__ in,
                           __nv_bfloat16* __restrict__ oh,
                           __nv_bfloat16* __restrict__ ol, int n)
{
    int i = blockIdx.x * blockDim.x + threadIdx.x;
    if (i >= n) return;
    float v = in[i];
    __nv_bfloat16 h = __float2bfloat16_rn(v);
    float r = v - __bfloat162float(h);
    oh[i] = h;
    ol[i] = __float2bfloat16_rn(r);
}

__global__ void conv_split_tr(const float* __restrict__ in,
                              __nv_bfloat16* __restrict__ oh,
                              __nv_bfloat16* __restrict__ ol, int K, int N)
{
    int i = blockIdx.x * blockDim.x + threadIdx.x;
    if (i >= K * N) return;
    int k = i / N, n = i % N;
    float v = in[i];
    __nv_bfloat16 h = __float2bfloat16_rn(v);
    float r = v - __bfloat162float(h);
    oh[(size_t)n * K + k] = h;
    ol[(size_t)n * K + k] = __float2bfloat16_rn(r);
}

// ======================================================================
// HMMA GEMM, bf16 split. Block tile 128(M)x256(N), 256 threads, 8 warps
// in 2(M)x4(N), warp tile 64x64 -> fragment-LDS intensity doubled vs 32x32.
// ======================================================================
#define LDKB 144                       // padded row bytes
#define ATILE (128 * LDKB)             // 18432
#define BTILE (256 * LDKB)             // 36864
#define BUFSZ (2 * ATILE + 2 * BTILE)  // 110592
#define AOFF(buf, v) ((buf) * BUFSZ + (v) * ATILE)
#define BOFF(buf, v) ((buf) * BUFSZ + 2 * ATILE + (v) * BTILE)
#define SMEM_GT (2 * BUFSZ)            // 221184

__global__ void __launch_bounds__(256, 1) gemm_tc_mma(
    const __nv_bfloat16* __restrict__ Ah, const __nv_bfloat16* __restrict__ Al,
    const __nv_bfloat16* __restrict__ Bh, const __nv_bfloat16* __restrict__ Bl,
    const float* __restrict__ bias, float* __restrict__ Cout,
    int M, int N, int K, int mode)
{
    extern __shared__ char smc[];
    const uint32_t sbase = smem_u32(smc);
    const int tid  = threadIdx.x;
    const int lane = tid & 31;
    const int wid  = tid >> 5;
    const int wm   = wid & 1;        // 0..1  (64 M-rows each)
    const int wn   = wid >> 1;       // 0..3  (64 N-cols each)
    const int bm = blockIdx.y * 128;
    const int bn = blockIdx.x * 256;

    const char* gA[2] = { (const char*)(Ah + (size_t)bm * K),
                          (const char*)(Al + (size_t)bm * K) };
    const char* gB[2] = { (const char*)(Bh + (size_t)bn * K),
                          (const char*)(Bl + (size_t)bn * K) };

    const int nk = K / 64;

    auto issue_chunk = [&](int k0, int buf) {
#pragma unroll
        for (int v = 0; v < 2; v++) {
#pragma unroll
            for (int j = 0; j < 4; j++) {           // A: 128 rows x 8 c16
                const int idx = j * 256 + tid;
                const int row = idx >> 3, c16 = idx & 7;
                cp16(sbase + AOFF(buf, v) + row * LDKB + c16 * 16,
                     gA[v] + (size_t)row * (K * 2) + k0 * 2 + c16 * 16);
            }
#pragma unroll
            for (int j = 0; j < 8; j++) {           // B: 256 rows x 8 c16
                const int idx = j * 256 + tid;
                const int row = idx >> 3, c16 = idx & 7;
                cp16(sbase + BOFF(buf, v) + row * LDKB + c16 * 16,
                     gB[v] + (size_t)row * (K * 2) + k0 * 2 + c16 * 16);
            }
        }
    };

    issue_chunk(0, 0); CP_COMMIT();
    if (nk > 1) { issue_chunk(64, 1); }
    CP_COMMIT();

    float acc[4][8][4];
#pragma unroll
    for (int i = 0; i < 4; i++)
#pragma unroll
        for (int j = 0; j < 8; j++)
#pragma unroll
            for (int q = 0; q < 4; q++) acc[i][j][q] = 0.f;

    const int lr = lane >> 2;
    const int lc = (lane & 3) * 2;

    for (int it = 0; it < nk; ++it) {
        const int buf = it & 1;
        CP_WAIT1();
        __syncthreads();

        const char* sA[2] = { smc + AOFF(buf, 0), smc + AOFF(buf, 1) };
        const char* sB[2] = { smc + BOFF(buf, 0), smc + BOFF(buf, 1) };

#pragma unroll
        for (int kk = 0; kk < 4; kk++) {
            const int kb = kk * 32 + lc * 2;
            uint32_t af[2][4][4];
#pragma unroll
            for (int v = 0; v < 2; v++)
#pragma unroll
                for (int i = 0; i < 4; i++) {
                    const int r0 = (wm * 64 + i * 16 + lr) * LDKB;
                    af[v][i][0] = *(const uint32_t*)(sA[v] + r0 + kb);
                    af[v][i][1] = *(const uint32_t*)(sA[v] + r0 + 8 * LDKB + kb);
                    af[v][i][2] = *(const uint32_t*)(sA[v] + r0 + kb + 16);
                    af[v][i][3] = *(const uint32_t*)(sA[v] + r0 + 8 * LDKB + kb + 16);
                }
            uint32_t bf[2][8][2];
#pragma unroll
            for (int v = 0; v < 2; v++)
#pragma unroll
                for (int j = 0; j < 8; j++) {
                    const int n0 = (wn * 64 + j * 8 + lr) * LDKB;
                    bf[v][j][0] = *(const uint32_t*)(sB[v] + n0 + kb);
                    bf[v][j][1] = *(const uint32_t*)(sB[v] + n0 + kb + 16);
                }
#pragma unroll
            for (int i = 0; i < 4; i++)
#pragma unroll
                for (int j = 0; j < 8; j++)
                    mma16816(acc[i][j], af[0][i], bf[0][j]);   // hi*hi
#pragma unroll
            for (int i = 0; i < 4; i++)
#pragma unroll
                for (int j = 0; j < 8; j++)
                    mma16816(acc[i][j], af[0][i], bf[1][j]);   // hi*lo
#pragma unroll
            for (int i = 0; i < 4; i++)
#pragma unroll
                for (int j = 0; j < 8; j++)
                    mma16816(acc[i][j], af[1][i], bf[0][j]);   // lo*hi
        }
        __syncthreads();
        if (it + 2 < nk) { issue_chunk((it + 2) * 64, buf); }
        CP_COMMIT();
    }

    // -------- epilogue --------
#pragma unroll
    for (int i = 0; i < 4; i++) {
        const int row0 = bm + wm * 64 + i * 16 + lr;
#pragma unroll
        for (int j = 0; j < 8; j++) {
            const int col = bn + wn * 64 + j * 8 + lc;
            const float b0 = bias[col], b1 = bias[col + 1];
            const float v00 = acc[i][j][0] + b0, v01 = acc[i][j][1] + b1;
            const float v10 = acc[i][j][2] + b0, v11 = acc[i][j][3] + b1;
            if (mode == 1) {
                *(float2*)&Cout[(size_t)row0 * N + col]       = make_float2(v00, v01);
                *(float2*)&Cout[(size_t)(row0 + 8) * N + col] = make_float2(v10, v11);
            } else {
                const int sel = col / D_;
                const int rem = col % D_;
                const int h   = rem / HD_;
                const int d0  = rem % HD_;
                const int bb0 = row0 >> 12, t0 = row0 & (T_ - 1);
                const int bb1 = (row0 + 8) >> 12, t1 = (row0 + 8) & (T_ - 1);
                if (sel == 2) {
                    const size_t hb0 = (size_t)(bb0 * H_ + h) * HD_;
                    const size_t hb1 = (size_t)(bb1 * H_ + h) * HD_;
                    __nv_bfloat16 h00 = __float2bfloat16_rn(v00);
                    __nv_bfloat16 h01 = __float2bfloat16_rn(v01);
                    __nv_bfloat16 h10 = __float2bfloat16_rn(v10);
                    __nv_bfloat16 h11 = __float2bfloat16_rn(v11);
                    g_vh[(hb0 + d0)     * T_ + t0] = h00;
                    g_vh[(hb0 + d0 + 1) * T_ + t0] = h01;
                    g_vh[(hb1 + d0)     * T_ + t1] = h10;
                    g_vh[(hb1 + d0 + 1) * T_ + t1] = h11;
                    g_vl[(hb0 + d0)     * T_ + t0] = __float2bfloat16_rn(v00 - __bfloat162float(h00));
                    g_vl[(hb0 + d0 + 1) * T_ + t0] = __float2bfloat16_rn(v01 - __bfloat162float(h01));
                    g_vl[(hb1 + d0)     * T_ + t1] = __float2bfloat16_rn(v10 - __bfloat162float(h10));
                    g_vl[(hb1 + d0 + 1) * T_ + t1] = __float2bfloat16_rn(v11 - __bfloat162float(h11));
                } else {
                    __nv_bfloat16* dh = (sel == 0) ? g_qh : g_kh;
                    __nv_bfloat16* dl = (sel == 0) ? g_ql : g_kl;
                    uint32_t hi, lo;
                    split2(v00, v01, hi, lo);
                    size_t off = ((size_t)(bb0 * H_ + h) * T_ + t0) * HD_ + d0;
                    *(uint32_t*)&dh[off] = hi; *(uint32_t*)&dl[off] = lo;
                    split2(v10, v11, hi, lo);
                    off = ((size_t)(bb1 * H_ + h) * T_ + t1) * HD_ + d0;
                    *(uint32_t*)&dh[off] = hi; *(uint32_t*)&dl[off] = lo;
                }
            }
        }
    }
    CP_WAIT0();
}

// ======================================================================
// Causal flash attention on HMMA (unchanged from round 7 passing version)
// ======================================================================
#define AP  72
#define APB (AP * 2)
#define SMEM_AT (128 * APB * 2 + 64 * APB * 4)

__global__ void __launch_bounds__(256, 1) attn_mma()
{
    extern __shared__ char sm[];
    char* sQh = sm;
    char* sQl = sm + 128 * APB;
    char* sKh = sQl + 128 * APB;
    char* sKl = sKh + 64 * APB;
    char* sVh = sKl + 64 * APB;
    char* sVl = sVh + 64 * APB;

    const int tid = threadIdx.x, lane = tid & 31, wid = tid >> 5;
    const int lr = lane >> 2, lq = lane & 3;
    const int qi = (int)gridDim.x - 1 - (int)blockIdx.x;
    const int h = blockIdx.y, b = blockIdx.z;
    const int qbase = qi * QT;

    const size_t bh = (size_t)(b * H_ + h) * T_;
    const char* qh = (const char*)(g_qh + (bh + qbase) * HD_);
    const char* ql = (const char*)(g_ql + (bh + qbase) * HD_);
    const char* kh = (const char*)(g_kh + bh * HD_);
    const char* kl = (const char*)(g_kl + bh * HD_);
    const char* vh = (const char*)(g_vh + bh * HD_);   // [hd][T]
    const char* vl = (const char*)(g_vl + bh * HD_);

#pragma unroll
    for (int p = 0; p < 4; p++) {
        const int idx = p * 256 + tid;
        const int row = idx >> 3, c16 = idx & 7;
        *(uint4*)(sQh + row * APB + c16 * 16) =
            *(const uint4*)(qh + (size_t)row * 128 + c16 * 16);
        *(uint4*)(sQl + row * APB + c16 * 16) =
            *(const uint4*)(ql + (size_t)row * 128 + c16 * 16);
    }
    __syncthreads();

    uint32_t qf[4][2][4];
    {
        const int r0 = (wid * 16 + lr) * APB;
#pragma unroll
        for (int kk = 0; kk < 4; kk++) {
            const int kbo = kk * 32 + lq * 4;
            qf[kk][0][0] = *(const uint32_t*)(sQh + r0 + kbo);
            qf[kk][0][1] = *(const uint32_t*)(sQh + r0 + 8 * APB + kbo);
            qf[kk][0][2] = *(const uint32_t*)(sQh + r0 + kbo + 16);
            qf[kk][0][3] = *(const uint32_t*)(sQh + r0 + 8 * APB + kbo + 16);
            qf[kk][1][0] = *(const uint32_t*)(sQl + r0 + kbo);
            qf[kk][1][1] = *(const uint32_t*)(sQl + r0 + 8 * APB + kbo);
            qf[kk][1][2] = *(const uint32_t*)(sQl + r0 + kbo + 16);
            qf[kk][1][3] = *(const uint32_t*)(sQl + r0 + 8 * APB + kbo + 16);
        }
    }

    float m[2] = {-1e30f, -1e30f}, l[2] = {0.f, 0.f};
    float o[8][4];
#pragma unroll
    for (int j = 0; j < 8; j++)
#pragma unroll
        for (int q = 0; q < 4; q++) o[j][q] = 0.f;

    const int nkt = qbase / KT + 2;
    const int rowmaxw = qbase + wid * 16 + 15;

    uint32_t bfh[2][8][2], bfl[2][8][2];

    for (int kt = 0; kt < nkt; kt++) {
        const int kb = kt * KT;
        __syncthreads();
#pragma unroll
        for (int p = 0; p < 2; p++) {
            const int idx = p * 256 + tid;
            const int row = idx >> 3, c16 = idx & 7;
            *(uint4*)(sKh + row * APB + c16 * 16) =
                *(const uint4*)(kh + (size_t)(kb + row) * 128 + c16 * 16);
            *(uint4*)(sKl + row * APB + c16 * 16) =
                *(const uint4*)(kl + (size_t)(kb + row) * 128 + c16 * 16);
            *(uint4*)(sVh + row * APB + c16 * 16) =
                *(const uint4*)(vh + (size_t)row * (T_ * 2) + kb * 2 + c16 * 16);
            *(uint4*)(sVl + row * APB + c16 * 16) =
                *(const uint4*)(vl + (size_t)row * (T_ * 2) + kb * 2 + c16 * 16);
        }
        __syncthreads();

        if (kb > rowmaxw) continue;

        float s[8][4];
#pragma unroll
        for (int j = 0; j < 8; j++)
#pragma unroll
            for (int q = 0; q < 4; q++) s[j][q] = 0.f;

        auto loadK = [&](int kk, int pb) {
            const int kbo = kk * 32 + lq * 4;
#pragma unroll
            for (int j = 0; j < 8; j++) {
                const int n0 = (j * 8 + lr) * APB;
                bfh[pb][j][0] = *(const uint32_t*)(sKh + n0 + kbo);
                bfh[pb][j][1] = *(const uint32_t*)(sKh + n0 + kbo + 16);
                bfl[pb][j][0] = *(const uint32_t*)(sKl + n0 + kbo);
                bfl[pb][j][1] = *(const uint32_t*)(sKl + n0 + kbo + 16);
            }
        };

        loadK(0, 0);
#pragma unroll
        for (int kk = 0; kk < 4; kk++) {
            const int pb = kk & 1;
            if (kk < 3) loadK(kk + 1, pb ^ 1);
#pragma unroll
            for (int j = 0; j < 8; j++) mma16816(s[j], qf[kk][0], bfh[pb][j]);
#pragma unroll
            for (int j = 0; j < 8; j++) mma16816(s[j], qf[kk][0], bfl[pb][j]);
#pragma unroll
            for (int j = 0; j < 8; j++) mma16816(s[j], qf[kk][1], bfh[pb][j]);
        }

        const bool needmask = (kb + 63) > (qbase + wid * 16);
        if (needmask) {
            const int row_a = qbase + wid * 16 + lr;
#pragma unroll
            for (int j = 0; j < 8; j++) {
                const int col0 = kb + j * 8 + lq * 2;
                s[j][0] = (col0     <= row_a)     ? s[j][0] * SCALE_ : -1e30f;
                s[j][1] = (col0 + 1 <= row_a)     ? s[j][1] * SCALE_ : -1e30f;
                s[j][2] = (col0     <= row_a + 8) ? s[j][2] * SCALE_ : -1e30f;
                s[j][3] = (col0 + 1 <= row_a + 8) ? s[j][3] * SCALE_ : -1e30f;
            }
        } else {
#pragma unroll
            for (int j = 0; j < 8; j++)
#pragma unroll
                for (int q = 0; q < 4; q++) s[j][q] *= SCALE_;
        }

#pragma unroll
        for (int r = 0; r < 2; r++) {
            float mx = -1e30f;
#pragma unroll
            for (int j = 0; j < 8; j++)
                mx = fmaxf(mx, fmaxf(s[j][2 * r], s[j][2 * r + 1]));
            mx = fmaxf(mx, __shfl_xor_sync(0xffffffffu, mx, 1));
            mx = fmaxf(mx, __shfl_xor_sync(0xffffffffu, mx, 2));
            const float mnew = fmaxf(m[r], mx);
            const float corr = __expf(m[r] - mnew);
            float sum = 0.f;
#pragma unroll
            for (int j = 0; j < 8; j++) {
                const float p0 = __expf(s[j][2 * r]     - mnew);
                const float p1 = __expf(s[j][2 * r + 1] - mnew);
                s[j][2 * r] = p0; s[j][2 * r + 1] = p1;
                sum += p0 + p1;
            }
            sum += __shfl_xor_sync(0xffffffffu, sum, 1);
            sum += __shfl_xor_sync(0xffffffffu, sum, 2);
            l[r] = l[r] * corr + sum;
            m[r] = mnew;
#pragma unroll
            for (int j = 0; j < 8; j++) {
                o[j][2 * r] *= corr; o[j][2 * r + 1] *= corr;
            }
        }

        uint32_t ph0[8], ph1[8], pl0[8], pl1[8];
#pragma unroll
        for (int j = 0; j < 8; j++) {
            split2(s[j][0], s[j][1], ph0[j], pl0[j]);
            split2(s[j][2], s[j][3], ph1[j], pl1[j]);
        }

        auto loadV = [&](int kk, int pb) {
            const int kbo = kk * 32 + lq * 4;
#pragma unroll
            for (int jn = 0; jn < 8; jn++) {
                const int n0 = (jn * 8 + lr) * APB;
                bfh[pb][jn][0] = *(const uint32_t*)(sVh + n0 + kbo);
                bfh[pb][jn][1] = *(const uint32_t*)(sVh + n0 + kbo + 16);
                bfl[pb][jn][0] = *(const uint32_t*)(sVl + n0 + kbo);
                bfl[pb][jn][1] = *(const uint32_t*)(sVl + n0 + kbo + 16);
            }
        };

        loadV(0, 0);
#pragma unroll
        for (int kk = 0; kk < 4; kk++) {
            const int pb = kk & 1;
            if (kk < 3) loadV(kk + 1, pb ^ 1);
            uint32_t a_h[4] = { ph0[2 * kk], ph1[2 * kk], ph0[2 * kk + 1], ph1[2 * kk + 1] };
            uint32_t a_l[4] = { pl0[2 * kk], pl1[2 * kk], pl0[2 * kk + 1], pl1[2 * kk + 1] };
#pragma unroll
            for (int jn = 0; jn < 8; jn++) mma16816(o[jn], a_h, bfh[pb][jn]);
#pragma unroll
            for (int jn = 0; jn < 8; jn++) mma16816(o[jn], a_h, bfl[pb][jn]);
#pragma unroll
            for (int jn = 0; jn < 8; jn++) mma16816(o[jn], a_l, bfh[pb][jn]);
        }
    }

    const float inv0 = 1.f / l[0], inv1 = 1.f / l[1];
    const int t0 = qbase + wid * 16 + lr;
    const int t1 = t0 + 8;
#pragma unroll
    for (int jn = 0; jn < 8; jn++) {
        const int d = h * HD_ + jn * 8 + lq * 2;
        uint32_t hi, lo;
        split2(o[jn][0] * inv0, o[jn][1] * inv0, hi, lo);
        size_t off = (size_t)(b * T_ + t0) * D_ + d;
        *(uint32_t*)&g_ah[off] = hi; *(uint32_t*)&g_al[off] = lo;
        split2(o[jn][2] * inv1, o[jn][3] * inv1, hi, lo);
        off = (size_t)(b * T_ + t1) * D_ + d;
        *(uint32_t*)&g_ah[off] = hi; *(uint32_t*)&g_al[off] = lo;
    }
}

// ======================================================================
extern "C" void kernel_launch(void* const* d_in, const int* in_sizes, int n_in,
                              void* d_out, int out_size)
{
    const float* x      = (const float*)d_in[0];
    const float* W_qkv  = (const float*)d_in[1];
    const float* b_qkv  = (const float*)d_in[2];
    const float* W_out  = (const float*)d_in[3];
    const float* b_out  = (const float*)d_in[4];
    float* out = (float*)d_out;

    __nv_bfloat16 *xh, *xl, *ah, *al, *wqh, *wql, *woh, *wol;
    cudaGetSymbolAddress((void**)&xh,  g_xh);
    cudaGetSymbolAddress((void**)&xl,  g_xl);
    cudaGetSymbolAddress((void**)&ah,  g_ah);
    cudaGetSymbolAddress((void**)&al,  g_al);
    cudaGetSymbolAddress((void**)&wqh, g_wqh);
    cudaGetSymbolAddress((void**)&wql, g_wql);
    cudaGetSymbolAddress((void**)&woh, g_woh);
    cudaGetSymbolAddress((void**)&wol, g_wol);

    cudaFuncSetAttribute(gemm_tc_mma, cudaFuncAttributeMaxDynamicSharedMemorySize, SMEM_GT);
    cudaFuncSetAttribute(attn_mma,    cudaFuncAttributeMaxDynamicSharedMemorySize, SMEM_AT);

    const int nX = B_ * T_ * D_;

    conv_split<<<(nX + 255) / 256, 256>>>(x, xh, xl, nX);
    conv_split_tr<<<(D_ * 3 * D_ + 255) / 256, 256>>>(W_qkv, wqh, wql, D_, 3 * D_);
    conv_split_tr<<<(D_ * D_ + 255) / 256, 256>>>(W_out, woh, wol, D_, D_);

    {
        dim3 grid((3 * D_) / 256, (B_ * T_) / 128);
        gemm_tc_mma<<<grid, 256, SMEM_GT>>>(xh, xl, wqh, wql, b_qkv, nullptr,
                                            B_ * T_, 3 * D_, D_, 0);
    }
    {
        dim3 grid(T_ / QT, H_, B_);
        attn_mma<<<grid, 256, SMEM_AT>>>();
    }
    {
        dim3 grid(D_ / 256, (B_ * T_) / 128);
        gemm_tc_mma<<<grid, 256, SMEM_GT>>>(ah, al, woh, wol, b_out, out,
                                            B_ * T_, D_, D_, 1);
    }
}